// round 1
// baseline (speedup 1.0000x reference)
#include <cuda_runtime.h>

#define BB 8
#define NN 16384
#define NPT 2048
#define NS 32
#define CIN 64
#define ROWS (BB*NPT*NS)   /* 524288 */
#define EPSV 1e-5f
#define INV_ROWS (1.0f/524288.0f)

// ---------------- static device scratch (no runtime allocation) ----------------
__device__ float4 g_pxyz[BB*NN];                       // packed (x,y,z,|p|^2)
__device__ float  g_ptst[(size_t)BB*NN*CIN];           // points transposed [b][n][c]
__device__ int    g_idx[BB*NPT*NS];                    // knn indices
__device__ float  g_h1[(size_t)ROWS*64];               // pre-BN layer1 out
__device__ float  g_h2[(size_t)ROWS*64];               // pre-BN layer2 out
__device__ float  g_h3[(size_t)ROWS*128];              // pre-BN layer3 out
__device__ float  g_stats[512];                        // S1[64] Q1[64] S2[64] Q2[64] S3[128] Q3[128]

// ---------------- prep: zero stats + pack xyz with |p|^2 ----------------
__global__ void k_prep(const float* __restrict__ xyz) {
    int i = blockIdx.x*256 + threadIdx.x;
    if (i < 512) g_stats[i] = 0.0f;
    if (i >= BB*NN) return;
    int b = i >> 14, n = i & (NN-1);
    float x = xyz[(b*3+0)*NN + n];
    float y = xyz[(b*3+1)*NN + n];
    float z = xyz[(b*3+2)*NN + n];
    g_pxyz[i] = make_float4(x, y, z, x*x + y*y + z*z);
}

// ---------------- transpose points (B,C,N) -> (B,N,C) ----------------
__global__ void k_transpose(const float* __restrict__ pts) {
    int i = blockIdx.x*256 + threadIdx.x;
    if (i >= BB*NN*16) return;
    int cg = (i & 15) * 4;
    int bn = i >> 4;
    int b = bn >> 14, n = bn & (NN-1);
    const float* src = pts + ((size_t)(b*CIN + cg))*NN + n;
    float4 v = make_float4(src[0], src[NN], src[2*NN], src[3*NN]);
    *(float4*)&g_ptst[(size_t)bn*64 + cg] = v;
}

// ---------------- output part 1: gathered centroids (B,3,NPT) ----------------
__global__ void k_gatherq(const float* __restrict__ xyz, const int* __restrict__ sidx,
                          float* __restrict__ outq) {
    int i = blockIdx.x*256 + threadIdx.x;
    if (i >= BB*3*NPT) return;
    int p = i & (NPT-1);
    int bc = i >> 11;
    outq[i] = xyz[bc*NN + sidx[p]];
}

// ---------------- knn flush: merge <=64 buffered candidates into sorted top-32 ----------------
__device__ __forceinline__ void knn_flush(unsigned long long& top, int& cnt,
                                          unsigned long long& thr,
                                          unsigned long long* cb,
                                          unsigned long long* nt, int lane) {
    const unsigned long long INFK = ~0ull;
    unsigned long long e1 = (lane      < cnt) ? cb[lane]      : INFK;
    unsigned long long e2 = (lane + 32 < cnt) ? cb[lane + 32] : INFK;
    int r0 = 0, r1 = 0, r2 = 0;
    #pragma unroll 8
    for (int j = 0; j < 32; ++j) {
        unsigned long long kj = __shfl_sync(0xffffffffu, top, j);
        r0 += (kj < top); r1 += (kj < e1); r2 += (kj < e2);
    }
    #pragma unroll 8
    for (int j = 0; j < 64; ++j) {
        unsigned long long kj = (j < cnt) ? cb[j] : INFK;
        r0 += (kj < top); r1 += (kj < e1); r2 += (kj < e2);
    }
    nt[lane] = INFK;
    __syncwarp();
    if (top != INFK && r0 < 32) nt[r0] = top;
    if (e1  != INFK && r1 < 32) nt[r1] = e1;
    if (e2  != INFK && r2 < 32) nt[r2] = e2;
    __syncwarp();
    top = nt[lane];
    cnt = 0;
    thr = __shfl_sync(0xffffffffu, top, 31);
    __syncwarp();
}

// ---------------- knn: 16 queries/block (2 per warp), smem point tiles ----------------
__global__ __launch_bounds__(256) void k_knn(const float* __restrict__ xyz,
                                             const int* __restrict__ sidx) {
    __shared__ float4 sp[2048];
    __shared__ unsigned long long cbuf[16*64];
    __shared__ unsigned long long ntop[8*32];
    int tid = threadIdx.x, lane = tid & 31, w = tid >> 5;
    int b = blockIdx.y;

    unsigned long long top[2], thr[2];
    int cnt[2];
    float qx[2], qy[2], qz[2], qq[2];
    #pragma unroll
    for (int qi = 0; qi < 2; ++qi) {
        int qg = blockIdx.x*16 + w*2 + qi;
        int s = sidx[qg];
        qx[qi] = xyz[(b*3+0)*NN + s];
        qy[qi] = xyz[(b*3+1)*NN + s];
        qz[qi] = xyz[(b*3+2)*NN + s];
        qq[qi] = qx[qi]*qx[qi] + qy[qi]*qy[qi] + qz[qi]*qz[qi];
        top[qi] = ~0ull; thr[qi] = ~0ull; cnt[qi] = 0;
    }

    for (int t = 0; t < NN; t += 2048) {
        __syncthreads();
        #pragma unroll
        for (int j = 0; j < 8; ++j)
            sp[tid + j*256] = g_pxyz[b*NN + t + tid + j*256];
        __syncthreads();
        #pragma unroll
        for (int qi = 0; qi < 2; ++qi) {
            unsigned long long* cb = &cbuf[(w*2+qi)*64];
            unsigned long long* nt = &ntop[w*32];
            float qxv = qx[qi], qyv = qy[qi], qzv = qz[qi], qqv = qq[qi];
            unsigned long long tk = thr[qi], tp = top[qi];
            int c = cnt[qi];
            for (int j = lane; j < 2048; j += 32) {
                float4 p = sp[j];
                float dot = qxv*p.x + qyv*p.y + qzv*p.z;
                float d2 = (qqv + p.w) - 2.0f*dot;
                unsigned u = __float_as_uint(d2);
                u = (u & 0x80000000u) ? ~u : (u | 0x80000000u);
                unsigned long long key = ((unsigned long long)u << 32) | (unsigned)(t + j);
                bool pred = key < tk;
                unsigned mask = __ballot_sync(0xffffffffu, pred);
                if (c + __popc(mask) > 64) {
                    knn_flush(tp, c, tk, cb, nt, lane);
                    pred = key < tk;
                    mask = __ballot_sync(0xffffffffu, pred);
                }
                if (pred) cb[c + __popc(mask & ((1u << lane) - 1u))] = key;
                c += __popc(mask);
            }
            thr[qi] = tk; top[qi] = tp; cnt[qi] = c;
        }
    }
    #pragma unroll
    for (int qi = 0; qi < 2; ++qi) {
        knn_flush(top[qi], cnt[qi], thr[qi], &cbuf[(w*2+qi)*64], &ntop[w*32], lane);
        int qg = blockIdx.x*16 + w*2 + qi;
        g_idx[(b*NPT + qg)*NS + lane] = (int)(top[qi] & 0xffffffffu);
    }
}

// ---------------- layer1: feat(67) @ W1^T + b1 -> g_h1 (pre-BN) ----------------
__global__ __launch_bounds__(256) void k_layer1(const float* __restrict__ xyz,
                                                const int* __restrict__ sidx,
                                                const float* __restrict__ W1,
                                                const float* __restrict__ b1) {
    __shared__ float ws[67*64];
    __shared__ float bs[64];
    int tid = threadIdx.x;
    for (int i = tid; i < 67*64; i += 256) {
        int o = i / 67, k = i - o*67;
        ws[k*64 + o] = W1[i];
    }
    if (tid < 64) bs[tid] = b1[tid];
    __syncthreads();
    int row = blockIdx.x*256 + tid;
    int b = row >> 16;
    int p = (row >> 5) & (NPT-1);
    int n = g_idx[row];
    float4 pc = g_pxyz[b*NN + n];
    int s = sidx[p];
    float f0 = pc.x - xyz[(b*3+0)*NN + s];
    float f1 = pc.y - xyz[(b*3+1)*NN + s];
    float f2 = pc.z - xyz[(b*3+2)*NN + s];
    float acc[64];
    #pragma unroll
    for (int o = 0; o < 64; ++o)
        acc[o] = bs[o] + f0*ws[o] + f1*ws[64+o] + f2*ws[128+o];
    const float* fin = &g_ptst[((size_t)(b*NN + n))*64];
    #pragma unroll 4
    for (int k = 0; k < 64; ++k) {
        float f = __ldg(&fin[k]);
        const float4* w4 = (const float4*)&ws[(k+3)*64];
        #pragma unroll
        for (int o4 = 0; o4 < 16; ++o4) {
            float4 wv = w4[o4];
            acc[o4*4+0] += f*wv.x; acc[o4*4+1] += f*wv.y;
            acc[o4*4+2] += f*wv.z; acc[o4*4+3] += f*wv.w;
        }
    }
    float4* op = (float4*)&g_h1[(size_t)row*64];
    #pragma unroll
    for (int o4 = 0; o4 < 16; ++o4)
        op[o4] = make_float4(acc[o4*4], acc[o4*4+1], acc[o4*4+2], acc[o4*4+3]);
}

// ---------------- layer2: relu(BN1(h1)) @ W2^T + b2 -> g_h2 ----------------
__global__ __launch_bounds__(256) void k_layer2(const float* __restrict__ W2,
                                                const float* __restrict__ b2,
                                                const float* __restrict__ g1,
                                                const float* __restrict__ be1) {
    __shared__ float ws[64*64];
    __shared__ float bs[64], sc[64], sh[64];
    int tid = threadIdx.x;
    for (int i = tid; i < 64*64; i += 256) {
        int o = i >> 6, k = i & 63;
        ws[k*64 + o] = W2[i];
    }
    if (tid < 64) {
        bs[tid] = b2[tid];
        float m = g_stats[tid] * INV_ROWS;
        float v = g_stats[64+tid] * INV_ROWS - m*m;
        float scv = g1[tid] * rsqrtf(v + EPSV);
        sc[tid] = scv;
        sh[tid] = be1[tid] - m*scv;
    }
    __syncthreads();
    int row = blockIdx.x*256 + tid;
    const float* hin = &g_h1[(size_t)row*64];
    float acc[64];
    #pragma unroll
    for (int o = 0; o < 64; ++o) acc[o] = bs[o];
    #pragma unroll 4
    for (int k = 0; k < 64; ++k) {
        float f = fmaxf(__ldg(&hin[k])*sc[k] + sh[k], 0.0f);
        const float4* w4 = (const float4*)&ws[k*64];
        #pragma unroll
        for (int o4 = 0; o4 < 16; ++o4) {
            float4 wv = w4[o4];
            acc[o4*4+0] += f*wv.x; acc[o4*4+1] += f*wv.y;
            acc[o4*4+2] += f*wv.z; acc[o4*4+3] += f*wv.w;
        }
    }
    float4* op = (float4*)&g_h2[(size_t)row*64];
    #pragma unroll
    for (int o4 = 0; o4 < 16; ++o4)
        op[o4] = make_float4(acc[o4*4], acc[o4*4+1], acc[o4*4+2], acc[o4*4+3]);
}

// ---------------- layer3 (split in 2 output halves): relu(BN2(h2)) @ W3^T + b3 -> g_h3 ----------------
__global__ __launch_bounds__(256) void k_layer3(const float* __restrict__ W3,
                                                const float* __restrict__ b3,
                                                const float* __restrict__ g2,
                                                const float* __restrict__ be2) {
    __shared__ float ws[64*64];
    __shared__ float bs[64], sc[64], sh[64];
    int tid = threadIdx.x;
    int oh = blockIdx.y;  // output half 0/1
    for (int i = tid; i < 64*64; i += 256) {
        int o = i >> 6, k = i & 63;
        ws[k*64 + o] = W3[(oh*64 + o)*64 + k];
    }
    if (tid < 64) {
        bs[tid] = b3[oh*64 + tid];
        float m = g_stats[128+tid] * INV_ROWS;
        float v = g_stats[192+tid] * INV_ROWS - m*m;
        float scv = g2[tid] * rsqrtf(v + EPSV);
        sc[tid] = scv;
        sh[tid] = be2[tid] - m*scv;
    }
    __syncthreads();
    int row = blockIdx.x*256 + tid;
    const float* hin = &g_h2[(size_t)row*64];
    float acc[64];
    #pragma unroll
    for (int o = 0; o < 64; ++o) acc[o] = bs[o];
    #pragma unroll 4
    for (int k = 0; k < 64; ++k) {
        float f = fmaxf(__ldg(&hin[k])*sc[k] + sh[k], 0.0f);
        const float4* w4 = (const float4*)&ws[k*64];
        #pragma unroll
        for (int o4 = 0; o4 < 16; ++o4) {
            float4 wv = w4[o4];
            acc[o4*4+0] += f*wv.x; acc[o4*4+1] += f*wv.y;
            acc[o4*4+2] += f*wv.z; acc[o4*4+3] += f*wv.w;
        }
    }
    float4* op = (float4*)&g_h3[(size_t)row*128 + oh*64];
    #pragma unroll
    for (int o4 = 0; o4 < 16; ++o4)
        op[o4] = make_float4(acc[o4*4], acc[o4*4+1], acc[o4*4+2], acc[o4*4+3]);
}

// ---------------- per-channel sum/sumsq reduction ----------------
template<int C, int WHICH>
__global__ __launch_bounds__(256) void k_reduce() {
    const float* h = (WHICH == 1) ? g_h1 : (WHICH == 2) ? g_h2 : g_h3;
    const int soff = (WHICH == 1) ? 0 : (WHICH == 2) ? 128 : 256;
    const int qoff = soff + C;
    const int G = C/4;
    int tid = threadIdx.x;
    int g = tid % G;
    const int rpb = 256 / G;
    size_t r = (size_t)blockIdx.x*rpb + (size_t)(tid / G);
    size_t rstr = (size_t)gridDim.x*rpb;
    float4 s = make_float4(0,0,0,0), q = make_float4(0,0,0,0);
    for (; r < (size_t)ROWS; r += rstr) {
        float4 v = *(const float4*)&h[r*C + g*4];
        s.x += v.x; s.y += v.y; s.z += v.z; s.w += v.w;
        q.x += v.x*v.x; q.y += v.y*v.y; q.z += v.z*v.z; q.w += v.w*v.w;
    }
    __shared__ float ssum[C], ssq[C];
    if (tid < C) { ssum[tid] = 0.0f; ssq[tid] = 0.0f; }
    __syncthreads();
    atomicAdd(&ssum[g*4+0], s.x); atomicAdd(&ssum[g*4+1], s.y);
    atomicAdd(&ssum[g*4+2], s.z); atomicAdd(&ssum[g*4+3], s.w);
    atomicAdd(&ssq[g*4+0], q.x);  atomicAdd(&ssq[g*4+1], q.y);
    atomicAdd(&ssq[g*4+2], q.z);  atomicAdd(&ssq[g*4+3], q.w);
    __syncthreads();
    if (tid < C) {
        atomicAdd(&g_stats[soff + tid], ssum[tid]);
        atomicAdd(&g_stats[qoff + tid], ssq[tid]);
    }
}

// ---------------- final: max/min over samples, BN3 affine, transpose-store ----------------
__global__ __launch_bounds__(256) void k_final(const float* __restrict__ g3,
                                               const float* __restrict__ be3,
                                               float* __restrict__ outp) {
    int gi = blockIdx.x*256 + threadIdx.x;     // 524288 threads
    int cg = (gi & 31) * 4;
    int bp = gi >> 5;
    const float* base = &g_h3[((size_t)bp*NS)*128 + cg];
    float mxa[4] = {-3.4e38f, -3.4e38f, -3.4e38f, -3.4e38f};
    float mna[4] = { 3.4e38f,  3.4e38f,  3.4e38f,  3.4e38f};
    #pragma unroll 4
    for (int s = 0; s < NS; ++s) {
        float4 v = *(const float4*)(base + (size_t)s*128);
        mxa[0] = fmaxf(mxa[0], v.x); mna[0] = fminf(mna[0], v.x);
        mxa[1] = fmaxf(mxa[1], v.y); mna[1] = fminf(mna[1], v.y);
        mxa[2] = fmaxf(mxa[2], v.z); mna[2] = fminf(mna[2], v.z);
        mxa[3] = fmaxf(mxa[3], v.w); mna[3] = fminf(mna[3], v.w);
    }
    int b = bp >> 11, p = bp & (NPT-1);
    #pragma unroll
    for (int j = 0; j < 4; ++j) {
        int c = cg + j;
        float m = g_stats[256+c] * INV_ROWS;
        float v = g_stats[384+c] * INV_ROWS - m*m;
        float scv = g3[c] * rsqrtf(v + EPSV);
        float sh = be3[c] - m*scv;
        float pick = (scv >= 0.0f) ? mxa[j] : mna[j];
        outp[((size_t)b*128 + c)*NPT + p] = pick*scv + sh;
    }
}

// ---------------- launch ----------------
extern "C" void kernel_launch(void* const* d_in, const int* in_sizes, int n_in,
                              void* d_out, int out_size) {
    const float* xyz    = (const float*)d_in[0];
    const float* points = (const float*)d_in[1];
    const int*   sidx   = (const int*)d_in[2];
    const float* W1 = (const float*)d_in[3];
    const float* b1 = (const float*)d_in[4];
    const float* g1 = (const float*)d_in[5];
    const float* be1 = (const float*)d_in[6];
    const float* W2 = (const float*)d_in[7];
    const float* b2 = (const float*)d_in[8];
    const float* g2 = (const float*)d_in[9];
    const float* be2 = (const float*)d_in[10];
    const float* W3 = (const float*)d_in[11];
    const float* b3 = (const float*)d_in[12];
    const float* g3 = (const float*)d_in[13];
    const float* be3 = (const float*)d_in[14];

    float* outq = (float*)d_out;                 // (B,3,NPT)
    float* outp = outq + (size_t)BB*3*NPT;       // (B,128,NPT)

    k_prep<<<(BB*NN + 255)/256, 256>>>(xyz);
    k_transpose<<<(BB*NN*16 + 255)/256, 256>>>(points);
    k_gatherq<<<(BB*3*NPT + 255)/256, 256>>>(xyz, sidx, outq);
    k_knn<<<dim3(NPT/16, BB), 256>>>(xyz, sidx);
    k_layer1<<<ROWS/256, 256>>>(xyz, sidx, W1, b1);
    k_reduce<64, 1><<<2048, 256>>>();
    k_layer2<<<ROWS/256, 256>>>(W2, b2, g1, be1);
    k_reduce<64, 2><<<2048, 256>>>();
    k_layer3<<<dim3(ROWS/256, 2), 256>>>(W3, b3, g2, be2);
    k_reduce<128, 3><<<2048, 256>>>();
    k_final<<<ROWS/256, 256>>>(g3, be3, outp);
}

// round 2
// speedup vs baseline: 1.2261x; 1.2261x over previous
#include <cuda_runtime.h>

#define BB 8
#define NN 16384
#define NPT 2048
#define NS 32
#define CIN 64
#define ROWS (BB*NPT*NS)   /* 524288 */
#define EPSV 1e-5f
#define INV_ROWS (1.0f/524288.0f)

// ---------------- static device scratch ----------------
__device__ float4 g_pxyz[BB*NN];                       // packed (x,y,z,|p|^2)
__device__ float  g_ptst[(size_t)BB*NN*CIN];           // points transposed [b][n][c]
__device__ int    g_idx[BB*NPT*NS];                    // knn indices
__device__ float  g_h1[(size_t)ROWS*64];               // pre-BN layer1 out
__device__ float  g_h2[(size_t)ROWS*64];               // pre-BN layer2 out
__device__ float  g_h3[(size_t)ROWS*128];              // pre-BN layer3 out
__device__ float  g_mx[BB*NPT*128];                    // pre-BN pooled max
__device__ float  g_mn[BB*NPT*128];                    // pre-BN pooled min
__device__ float  g_stats[512];                        // S1 Q1 S2 Q2 S3[128] Q3[128]

// ---------------- prep: zero stats + pack xyz with |p|^2 ----------------
__global__ void k_prep(const float* __restrict__ xyz) {
    int i = blockIdx.x*256 + threadIdx.x;
    if (i < 512) g_stats[i] = 0.0f;
    if (i >= BB*NN) return;
    int b = i >> 14, n = i & (NN-1);
    float x = xyz[(b*3+0)*NN + n];
    float y = xyz[(b*3+1)*NN + n];
    float z = xyz[(b*3+2)*NN + n];
    g_pxyz[i] = make_float4(x, y, z, x*x + y*y + z*z);
}

// ---------------- transpose points (B,C,N) -> (B,N,C) ----------------
__global__ void k_transpose(const float* __restrict__ pts) {
    int i = blockIdx.x*256 + threadIdx.x;
    if (i >= BB*NN*16) return;
    int cg = (i & 15) * 4;
    int bn = i >> 4;
    int b = bn >> 14, n = bn & (NN-1);
    const float* src = pts + ((size_t)(b*CIN + cg))*NN + n;
    float4 v = make_float4(src[0], src[NN], src[2*NN], src[3*NN]);
    *(float4*)&g_ptst[(size_t)bn*64 + cg] = v;
}

// ---------------- output part 1: gathered centroids (B,3,NPT) ----------------
__global__ void k_gatherq(const float* __restrict__ xyz, const int* __restrict__ sidx,
                          float* __restrict__ outq) {
    int i = blockIdx.x*256 + threadIdx.x;
    if (i >= BB*3*NPT) return;
    int p = i & (NPT-1);
    int bc = i >> 11;
    outq[i] = xyz[bc*NN + sidx[p]];
}

// ---------------- knn flush: merge <=64 buffered candidates into sorted top-32 ----------------
__device__ __forceinline__ void knn_flush(unsigned long long& top, int& cnt, float& thr,
                                          unsigned long long* cb,
                                          unsigned long long* nt, int lane) {
    const unsigned long long INFK = ~0ull;
    unsigned long long e1 = (lane      < cnt) ? cb[lane]      : INFK;
    unsigned long long e2 = (lane + 32 < cnt) ? cb[lane + 32] : INFK;
    int r0 = 0, r1 = 0, r2 = 0;
    #pragma unroll 8
    for (int j = 0; j < 32; ++j) {
        unsigned long long kj = __shfl_sync(0xffffffffu, top, j);
        r0 += (kj < top); r1 += (kj < e1); r2 += (kj < e2);
    }
    #pragma unroll 8
    for (int j = 0; j < 64; ++j) {
        unsigned long long kj = (j < cnt) ? cb[j] : INFK;
        r0 += (kj < top); r1 += (kj < e1); r2 += (kj < e2);
    }
    nt[lane] = INFK;
    __syncwarp();
    if (top != INFK && r0 < 32) nt[r0] = top;
    if (e1  != INFK && r1 < 32) nt[r1] = e1;
    if (e2  != INFK && r2 < 32) nt[r2] = e2;
    __syncwarp();
    top = nt[lane];
    cnt = 0;
    unsigned long long k31 = __shfl_sync(0xffffffffu, top, 31);
    unsigned u = (unsigned)(k31 >> 32);
    float t;
    if (u == 0xFFFFFFFFu) {
        t = __int_as_float(0x7F800000);  // +inf
    } else {
        unsigned bits = (u & 0x80000000u) ? (u & 0x7FFFFFFFu) : ~u;
        t = __uint_as_float(bits);
    }
    thr = t;
    __syncwarp();
}

// ---------------- knn: 32 queries/block (4 per warp), smem point tiles ----------------
__global__ __launch_bounds__(256) void k_knn(const float* __restrict__ xyz,
                                             const int* __restrict__ sidx) {
    __shared__ float4 sp[1024];                       // 16KB
    __shared__ unsigned long long cbuf[32*64];        // 16KB
    __shared__ unsigned long long ntop[8*32];         // 2KB
    int tid = threadIdx.x, lane = tid & 31, w = tid >> 5;
    int b = blockIdx.y;
    unsigned lml = (1u << lane) - 1u;

    unsigned long long top[4];
    float thr[4];
    int cnt[4];
    float qx[4], qy[4], qz[4], qq[4];
    #pragma unroll
    for (int qi = 0; qi < 4; ++qi) {
        int qg = blockIdx.x*32 + w*4 + qi;
        int s = sidx[qg];
        qx[qi] = xyz[(b*3+0)*NN + s];
        qy[qi] = xyz[(b*3+1)*NN + s];
        qz[qi] = xyz[(b*3+2)*NN + s];
        qq[qi] = qx[qi]*qx[qi] + qy[qi]*qy[qi] + qz[qi]*qz[qi];
        top[qi] = ~0ull; thr[qi] = __int_as_float(0x7F800000); cnt[qi] = 0;
    }

    for (int t = 0; t < NN; t += 1024) {
        __syncthreads();
        #pragma unroll
        for (int j = 0; j < 4; ++j)
            sp[tid + j*256] = g_pxyz[b*NN + t + tid + j*256];
        __syncthreads();
        for (int j = lane; j < 1024; j += 32) {
            float4 p = sp[j];
            int gidx = t + j;
            #pragma unroll
            for (int qi = 0; qi < 4; ++qi) {
                float dot = qx[qi]*p.x + qy[qi]*p.y + qz[qi]*p.z;
                float d2 = (qq[qi] + p.w) - 2.0f*dot;
                bool pr = d2 < thr[qi];
                unsigned m = __ballot_sync(0xffffffffu, pr);
                if (m) {
                    unsigned long long* cb = &cbuf[(w*4+qi)*64];
                    int pc = __popc(m);
                    if (cnt[qi] + pc > 64) {
                        knn_flush(top[qi], cnt[qi], thr[qi], cb, &ntop[w*32], lane);
                        pr = d2 < thr[qi];
                        m = __ballot_sync(0xffffffffu, pr);
                        pc = __popc(m);
                    }
                    if (pr) {
                        unsigned u = __float_as_uint(d2);
                        u = (u & 0x80000000u) ? ~u : (u | 0x80000000u);
                        cb[cnt[qi] + __popc(m & lml)] =
                            ((unsigned long long)u << 32) | (unsigned)gidx;
                    }
                    cnt[qi] += pc;
                }
            }
        }
    }
    #pragma unroll
    for (int qi = 0; qi < 4; ++qi) {
        knn_flush(top[qi], cnt[qi], thr[qi], &cbuf[(w*4+qi)*64], &ntop[w*32], lane);
        int qg = blockIdx.x*32 + w*4 + qi;
        g_idx[(b*NPT + qg)*NS + lane] = (int)(top[qi] & 0xffffffffu);
    }
}

// ---------------- layer1: feat(67) @ W1^T + b1 -> g_h1 (pre-BN), two passes of 32 ch ----------------
__global__ __launch_bounds__(256) void k_layer1(const float* __restrict__ xyz,
                                                const int* __restrict__ sidx,
                                                const float* __restrict__ W1,
                                                const float* __restrict__ b1) {
    __shared__ float ws[67*64];
    __shared__ float bs[64];
    int tid = threadIdx.x;
    for (int i = tid; i < 67*64; i += 256) {
        int o = i / 67, k = i - o*67;
        ws[k*64 + o] = W1[i];
    }
    if (tid < 64) bs[tid] = b1[tid];
    __syncthreads();
    int row = blockIdx.x*256 + tid;
    int b = row >> 16;
    int p = (row >> 5) & (NPT-1);
    int n = g_idx[row];
    float4 pc = g_pxyz[b*NN + n];
    int s = sidx[p];
    float f0 = pc.x - xyz[(b*3+0)*NN + s];
    float f1 = pc.y - xyz[(b*3+1)*NN + s];
    float f2 = pc.z - xyz[(b*3+2)*NN + s];
    const float4* fin = (const float4*)&g_ptst[((size_t)(b*NN + n))*64];
    #pragma unroll
    for (int pass = 0; pass < 2; ++pass) {
        const int po = pass*32;
        float acc[32];
        #pragma unroll
        for (int o = 0; o < 32; ++o)
            acc[o] = bs[po+o] + f0*ws[po+o] + f1*ws[64+po+o] + f2*ws[128+po+o];
        #pragma unroll 4
        for (int k4 = 0; k4 < 16; ++k4) {
            float4 h4 = __ldg(&fin[k4]);
            float f[4] = {h4.x, h4.y, h4.z, h4.w};
            #pragma unroll
            for (int kk = 0; kk < 4; ++kk) {
                const float4* w4 = (const float4*)&ws[(3 + k4*4 + kk)*64 + po];
                #pragma unroll
                for (int o4 = 0; o4 < 8; ++o4) {
                    float4 wv = w4[o4];
                    acc[o4*4+0] += f[kk]*wv.x; acc[o4*4+1] += f[kk]*wv.y;
                    acc[o4*4+2] += f[kk]*wv.z; acc[o4*4+3] += f[kk]*wv.w;
                }
            }
        }
        float4* op = (float4*)&g_h1[(size_t)row*64 + po];
        #pragma unroll
        for (int o4 = 0; o4 < 8; ++o4)
            op[o4] = make_float4(acc[o4*4], acc[o4*4+1], acc[o4*4+2], acc[o4*4+3]);
    }
}

// ---------------- layer2: relu(BN1(h1)) @ W2^T + b2 -> g_h2, two passes ----------------
__global__ __launch_bounds__(256) void k_layer2(const float* __restrict__ W2,
                                                const float* __restrict__ b2,
                                                const float* __restrict__ g1,
                                                const float* __restrict__ be1) {
    __shared__ float ws[64*64];
    __shared__ float bs[64], sc[64], sh[64];
    int tid = threadIdx.x;
    for (int i = tid; i < 64*64; i += 256) {
        int o = i >> 6, k = i & 63;
        ws[k*64 + o] = W2[i];
    }
    if (tid < 64) {
        bs[tid] = b2[tid];
        float m = g_stats[tid] * INV_ROWS;
        float v = g_stats[64+tid] * INV_ROWS - m*m;
        float scv = g1[tid] * rsqrtf(v + EPSV);
        sc[tid] = scv;
        sh[tid] = be1[tid] - m*scv;
    }
    __syncthreads();
    size_t row = (size_t)blockIdx.x*256 + tid;
    const float4* hin = (const float4*)&g_h1[row*64];
    #pragma unroll
    for (int pass = 0; pass < 2; ++pass) {
        const int po = pass*32;
        float acc[32];
        #pragma unroll
        for (int o = 0; o < 32; ++o) acc[o] = bs[po+o];
        #pragma unroll 4
        for (int k4 = 0; k4 < 16; ++k4) {
            float4 h4 = __ldg(&hin[k4]);
            float4 s4 = *(const float4*)&sc[k4*4];
            float4 t4 = *(const float4*)&sh[k4*4];
            float f[4] = { fmaxf(h4.x*s4.x + t4.x, 0.0f), fmaxf(h4.y*s4.y + t4.y, 0.0f),
                           fmaxf(h4.z*s4.z + t4.z, 0.0f), fmaxf(h4.w*s4.w + t4.w, 0.0f) };
            #pragma unroll
            for (int kk = 0; kk < 4; ++kk) {
                const float4* w4 = (const float4*)&ws[(k4*4 + kk)*64 + po];
                #pragma unroll
                for (int o4 = 0; o4 < 8; ++o4) {
                    float4 wv = w4[o4];
                    acc[o4*4+0] += f[kk]*wv.x; acc[o4*4+1] += f[kk]*wv.y;
                    acc[o4*4+2] += f[kk]*wv.z; acc[o4*4+3] += f[kk]*wv.w;
                }
            }
        }
        float4* op = (float4*)&g_h2[row*64 + po];
        #pragma unroll
        for (int o4 = 0; o4 < 8; ++o4)
            op[o4] = make_float4(acc[o4*4], acc[o4*4+1], acc[o4*4+2], acc[o4*4+3]);
    }
}

// ---------------- layer3 (2 output halves): relu(BN2(h2)) @ W3^T + b3 -> g_h3, two passes ----------------
__global__ __launch_bounds__(256) void k_layer3(const float* __restrict__ W3,
                                                const float* __restrict__ b3,
                                                const float* __restrict__ g2,
                                                const float* __restrict__ be2) {
    __shared__ float ws[64*64];
    __shared__ float bs[64], sc[64], sh[64];
    int tid = threadIdx.x;
    int oh = blockIdx.y;
    for (int i = tid; i < 64*64; i += 256) {
        int o = i >> 6, k = i & 63;
        ws[k*64 + o] = W3[(oh*64 + o)*64 + k];
    }
    if (tid < 64) {
        bs[tid] = b3[oh*64 + tid];
        float m = g_stats[128+tid] * INV_ROWS;
        float v = g_stats[192+tid] * INV_ROWS - m*m;
        float scv = g2[tid] * rsqrtf(v + EPSV);
        sc[tid] = scv;
        sh[tid] = be2[tid] - m*scv;
    }
    __syncthreads();
    size_t row = (size_t)blockIdx.x*256 + tid;
    const float4* hin = (const float4*)&g_h2[row*64];
    #pragma unroll
    for (int pass = 0; pass < 2; ++pass) {
        const int po = pass*32;
        float acc[32];
        #pragma unroll
        for (int o = 0; o < 32; ++o) acc[o] = bs[po+o];
        #pragma unroll 4
        for (int k4 = 0; k4 < 16; ++k4) {
            float4 h4 = __ldg(&hin[k4]);
            float4 s4 = *(const float4*)&sc[k4*4];
            float4 t4 = *(const float4*)&sh[k4*4];
            float f[4] = { fmaxf(h4.x*s4.x + t4.x, 0.0f), fmaxf(h4.y*s4.y + t4.y, 0.0f),
                           fmaxf(h4.z*s4.z + t4.z, 0.0f), fmaxf(h4.w*s4.w + t4.w, 0.0f) };
            #pragma unroll
            for (int kk = 0; kk < 4; ++kk) {
                const float4* w4 = (const float4*)&ws[(k4*4 + kk)*64 + po];
                #pragma unroll
                for (int o4 = 0; o4 < 8; ++o4) {
                    float4 wv = w4[o4];
                    acc[o4*4+0] += f[kk]*wv.x; acc[o4*4+1] += f[kk]*wv.y;
                    acc[o4*4+2] += f[kk]*wv.z; acc[o4*4+3] += f[kk]*wv.w;
                }
            }
        }
        float4* op = (float4*)&g_h3[row*128 + oh*64 + po];
        #pragma unroll
        for (int o4 = 0; o4 < 8; ++o4)
            op[o4] = make_float4(acc[o4*4], acc[o4*4+1], acc[o4*4+2], acc[o4*4+3]);
    }
}

// ---------------- per-channel sum/sumsq reduction (layers 1,2) ----------------
template<int WHICH>
__global__ __launch_bounds__(256) void k_reduce() {
    const float* h = (WHICH == 1) ? g_h1 : g_h2;
    const int soff = (WHICH == 1) ? 0 : 128;
    const int qoff = soff + 64;
    const int G = 16;
    int tid = threadIdx.x;
    int g = tid % G;
    const int rpb = 16;
    size_t r = (size_t)blockIdx.x*rpb + (size_t)(tid / G);
    size_t rstr = (size_t)gridDim.x*rpb;
    float4 s = make_float4(0,0,0,0), q = make_float4(0,0,0,0);
    for (; r < (size_t)ROWS; r += rstr) {
        float4 v = *(const float4*)&h[r*64 + g*4];
        s.x += v.x; s.y += v.y; s.z += v.z; s.w += v.w;
        q.x += v.x*v.x; q.y += v.y*v.y; q.z += v.z*v.z; q.w += v.w*v.w;
    }
    __shared__ float ssum[64], ssq[64];
    if (tid < 64) { ssum[tid] = 0.0f; ssq[tid] = 0.0f; }
    __syncthreads();
    atomicAdd(&ssum[g*4+0], s.x); atomicAdd(&ssum[g*4+1], s.y);
    atomicAdd(&ssum[g*4+2], s.z); atomicAdd(&ssum[g*4+3], s.w);
    atomicAdd(&ssq[g*4+0], q.x);  atomicAdd(&ssq[g*4+1], q.y);
    atomicAdd(&ssq[g*4+2], q.z);  atomicAdd(&ssq[g*4+3], q.w);
    __syncthreads();
    if (tid < 64) {
        atomicAdd(&g_stats[soff + tid], ssum[tid]);
        atomicAdd(&g_stats[qoff + tid], ssq[tid]);
    }
}

// ---------------- pool: one pass over h3: max/min over samples + sum/sumsq stats ----------------
__global__ __launch_bounds__(256) void k_pool() {
    int gi = blockIdx.x*256 + threadIdx.x;     // 524288 threads
    int tid = threadIdx.x;
    int cg = (gi & 31) * 4;
    int bp = gi >> 5;
    const float* base = &g_h3[((size_t)bp*NS)*128 + cg];
    float mxa[4] = {-3.4e38f, -3.4e38f, -3.4e38f, -3.4e38f};
    float mna[4] = { 3.4e38f,  3.4e38f,  3.4e38f,  3.4e38f};
    float sa[4] = {0,0,0,0}, qa[4] = {0,0,0,0};
    #pragma unroll 4
    for (int s = 0; s < NS; ++s) {
        float4 v = *(const float4*)(base + (size_t)s*128);
        mxa[0] = fmaxf(mxa[0], v.x); mna[0] = fminf(mna[0], v.x); sa[0] += v.x; qa[0] += v.x*v.x;
        mxa[1] = fmaxf(mxa[1], v.y); mna[1] = fminf(mna[1], v.y); sa[1] += v.y; qa[1] += v.y*v.y;
        mxa[2] = fmaxf(mxa[2], v.z); mna[2] = fminf(mna[2], v.z); sa[2] += v.z; qa[2] += v.z*v.z;
        mxa[3] = fmaxf(mxa[3], v.w); mna[3] = fminf(mna[3], v.w); sa[3] += v.w; qa[3] += v.w*v.w;
    }
    *(float4*)&g_mx[(size_t)bp*128 + cg] = make_float4(mxa[0], mxa[1], mxa[2], mxa[3]);
    *(float4*)&g_mn[(size_t)bp*128 + cg] = make_float4(mna[0], mna[1], mna[2], mna[3]);
    __shared__ float ssum[128], ssq[128];
    if (tid < 128) { ssum[tid] = 0.0f; ssq[tid] = 0.0f; }
    __syncthreads();
    #pragma unroll
    for (int j = 0; j < 4; ++j) {
        atomicAdd(&ssum[cg+j], sa[j]);
        atomicAdd(&ssq[cg+j], qa[j]);
    }
    __syncthreads();
    if (tid < 128)      atomicAdd(&g_stats[256 + tid], ssum[tid]);
    else                atomicAdd(&g_stats[384 + tid - 128], ssq[tid - 128]);
}

// ---------------- apply BN3 affine to pooled max/min, transpose-store ----------------
__global__ __launch_bounds__(256) void k_apply(const float* __restrict__ g3,
                                               const float* __restrict__ be3,
                                               float* __restrict__ outp) {
    int i = blockIdx.x*256 + threadIdx.x;      // 16384*128
    int c = i & 127;
    int bp = i >> 7;
    int b = bp >> 11, p = bp & (NPT-1);
    float m = g_stats[256+c] * INV_ROWS;
    float v = g_stats[384+c] * INV_ROWS - m*m;
    float scv = g3[c] * rsqrtf(v + EPSV);
    float sh = be3[c] - m*scv;
    float pick = (scv >= 0.0f) ? g_mx[i] : g_mn[i];
    outp[((size_t)b*128 + c)*NPT + p] = pick*scv + sh;
}

// ---------------- launch ----------------
extern "C" void kernel_launch(void* const* d_in, const int* in_sizes, int n_in,
                              void* d_out, int out_size) {
    const float* xyz    = (const float*)d_in[0];
    const float* points = (const float*)d_in[1];
    const int*   sidx   = (const int*)d_in[2];
    const float* W1 = (const float*)d_in[3];
    const float* b1 = (const float*)d_in[4];
    const float* g1 = (const float*)d_in[5];
    const float* be1 = (const float*)d_in[6];
    const float* W2 = (const float*)d_in[7];
    const float* b2 = (const float*)d_in[8];
    const float* g2 = (const float*)d_in[9];
    const float* be2 = (const float*)d_in[10];
    const float* W3 = (const float*)d_in[11];
    const float* b3 = (const float*)d_in[12];
    const float* g3 = (const float*)d_in[13];
    const float* be3 = (const float*)d_in[14];

    float* outq = (float*)d_out;                 // (B,3,NPT)
    float* outp = outq + (size_t)BB*3*NPT;       // (B,128,NPT)

    k_prep<<<(BB*NN + 255)/256, 256>>>(xyz);
    k_transpose<<<(BB*NN*16 + 255)/256, 256>>>(points);
    k_gatherq<<<(BB*3*NPT + 255)/256, 256>>>(xyz, sidx, outq);
    k_knn<<<dim3(NPT/32, BB), 256>>>(xyz, sidx);
    k_layer1<<<ROWS/256, 256>>>(xyz, sidx, W1, b1);
    k_reduce<1><<<2048, 256>>>();
    k_layer2<<<ROWS/256, 256>>>(W2, b2, g1, be1);
    k_reduce<2><<<2048, 256>>>();
    k_layer3<<<dim3(ROWS/256, 2), 256>>>(W3, b3, g2, be2);
    k_pool<<<ROWS/256, 256>>>();
    k_apply<<<(BB*NPT*128)/256, 256>>>(g3, be3, outp);
}

// round 3
// speedup vs baseline: 1.4618x; 1.1922x over previous
#include <cuda_runtime.h>

#define BB 8
#define NN 16384
#define NPT 2048
#define NS 32
#define CIN 64
#define ROWS (BB*NPT*NS)   /* 524288 */
#define EPSV 1e-5f
#define INV_ROWS (1.0f/524288.0f)

typedef unsigned long long ull;

// ---------------- static device scratch ----------------
__device__ float4 g_pxyz[BB*NN];                       // packed (x,y,z,0.5*|p|^2)
__device__ float  g_ptst[(size_t)BB*NN*CIN];           // points transposed [b][n][c]
__device__ int    g_idx[BB*NPT*NS];                    // knn indices
__device__ float  g_h1[(size_t)ROWS*64];               // pre-BN layer1 out
__device__ float  g_h2[(size_t)ROWS*64];               // pre-BN layer2 out
__device__ float  g_h3[(size_t)ROWS*128];              // pre-BN layer3 out
__device__ float  g_mx[BB*NPT*128];                    // pre-BN pooled max
__device__ float  g_mn[BB*NPT*128];                    // pre-BN pooled min
__device__ float  g_stats[512];                        // S1 Q1 S2 Q2 S3[128] Q3[128]

// ---------------- prep: zero stats + pack xyz with 0.5*|p|^2 ----------------
__global__ void k_prep(const float* __restrict__ xyz) {
    int i = blockIdx.x*256 + threadIdx.x;
    if (i < 512) g_stats[i] = 0.0f;
    if (i >= BB*NN) return;
    int b = i >> 14, n = i & (NN-1);
    float x = xyz[(b*3+0)*NN + n];
    float y = xyz[(b*3+1)*NN + n];
    float z = xyz[(b*3+2)*NN + n];
    g_pxyz[i] = make_float4(x, y, z, 0.5f*(x*x + y*y + z*z));
}

// ---------------- transpose points (B,C,N) -> (B,N,C) ----------------
__global__ void k_transpose(const float* __restrict__ pts) {
    int i = blockIdx.x*256 + threadIdx.x;
    if (i >= BB*NN*16) return;
    int cg = (i & 15) * 4;
    int bn = i >> 4;
    int b = bn >> 14, n = bn & (NN-1);
    const float* src = pts + ((size_t)(b*CIN + cg))*NN + n;
    float4 v = make_float4(src[0], src[NN], src[2*NN], src[3*NN]);
    *(float4*)&g_ptst[(size_t)bn*64 + cg] = v;
}

// ---------------- output part 1: gathered centroids (B,3,NPT) ----------------
__global__ void k_gatherq(const float* __restrict__ xyz, const int* __restrict__ sidx,
                          float* __restrict__ outq) {
    int i = blockIdx.x*256 + threadIdx.x;
    if (i >= BB*3*NPT) return;
    int p = i & (NPT-1);
    int bc = i >> 11;
    outq[i] = xyz[bc*NN + sidx[p]];
}

// ---------------- knn flush: merge <=64 buffered candidates into sorted top-32 ----------------
// keys are in half-distance domain; thr returned in half-distance domain
__device__ __forceinline__ void knn_flush(ull& top, int& cnt, float& thr,
                                          ull* cb, ull* nt, int lane) {
    const ull INFK = ~0ull;
    ull e1 = (lane      < cnt) ? cb[lane]      : INFK;
    ull e2 = (lane + 32 < cnt) ? cb[lane + 32] : INFK;
    int r0 = 0, r1 = 0, r2 = 0;
    #pragma unroll 8
    for (int j = 0; j < 32; ++j) {
        ull kj = __shfl_sync(0xffffffffu, top, j);
        r0 += (kj < top); r1 += (kj < e1); r2 += (kj < e2);
    }
    #pragma unroll 8
    for (int j = 0; j < 64; ++j) {
        ull kj = (j < cnt) ? cb[j] : INFK;
        r0 += (kj < top); r1 += (kj < e1); r2 += (kj < e2);
    }
    nt[lane] = INFK;
    __syncwarp();
    if (top != INFK && r0 < 32) nt[r0] = top;
    if (e1  != INFK && r1 < 32) nt[r1] = e1;
    if (e2  != INFK && r2 < 32) nt[r2] = e2;
    __syncwarp();
    top = nt[lane];
    cnt = 0;
    ull k31 = __shfl_sync(0xffffffffu, top, 31);
    unsigned u = (unsigned)(k31 >> 32);
    float t;
    if (u == 0xFFFFFFFFu) {
        t = __int_as_float(0x7F800000);  // +inf
    } else {
        unsigned bits = (u & 0x80000000u) ? (u & 0x7FFFFFFFu) : ~u;
        t = __uint_as_float(bits);
    }
    thr = t;
    __syncwarp();
}

__device__ __forceinline__ unsigned mono_map(float v) {
    unsigned u = __float_as_uint(v);
    return (u & 0x80000000u) ? ~u : (u | 0x80000000u);
}

// ---------------- knn: 16 queries/block (2 per warp), smem point tiles ----------------
__global__ __launch_bounds__(256) void k_knn(const float* __restrict__ xyz,
                                             const int* __restrict__ sidx) {
    __shared__ float4 sp[1024];                       // 16KB
    __shared__ ull cbuf[16*64];                       // 8KB
    __shared__ ull ntop[8*32];                        // 2KB
    int tid = threadIdx.x, lane = tid & 31, w = tid >> 5;
    int b = blockIdx.y;
    unsigned lml = (1u << lane) - 1u;
    ull* cb0 = &cbuf[(w*2+0)*64];
    ull* cb1 = &cbuf[(w*2+1)*64];
    ull* nt = &ntop[w*32];

    int qg = blockIdx.x*16 + w*2;
    int s0 = sidx[qg], s1 = sidx[qg+1];
    float qx0 = xyz[(b*3+0)*NN + s0], qy0 = xyz[(b*3+1)*NN + s0], qz0 = xyz[(b*3+2)*NN + s0];
    float qx1 = xyz[(b*3+0)*NN + s1], qy1 = xyz[(b*3+1)*NN + s1], qz1 = xyz[(b*3+2)*NN + s1];
    float c20 = 0.5f*(qx0*qx0 + qy0*qy0 + qz0*qz0);
    float c21 = 0.5f*(qx1*qx1 + qy1*qy1 + qz1*qz1);
    const float INFF = __int_as_float(0x7F800000);
    ull top0 = ~0ull, top1 = ~0ull;
    float thr0 = INFF, thr1 = INFF;
    float u0 = INFF, u1 = INFF;
    int c0 = 0, c1 = 0;

    for (int t = 0; t < NN; t += 1024) {
        __syncthreads();
        #pragma unroll
        for (int j = 0; j < 4; ++j)
            sp[tid + j*256] = g_pxyz[b*NN + t + tid + j*256];
        __syncthreads();
        for (int j = lane; j < 1024; j += 32) {
            if ((c0 | c1) > 32) {      // warp-uniform, rare
                if (c0 > 32) { knn_flush(top0, c0, thr0, cb0, nt, lane); u0 = thr0 - c20; }
                if (c1 > 32) { knn_flush(top1, c1, thr1, cb1, nt, lane); u1 = thr1 - c21; }
            }
            float4 p = sp[j];
            float d0 = __fmaf_rn(-qx0, p.x, p.w);
            d0 = __fmaf_rn(-qy0, p.y, d0);
            d0 = __fmaf_rn(-qz0, p.z, d0);
            float d1 = __fmaf_rn(-qx1, p.x, p.w);
            d1 = __fmaf_rn(-qy1, p.y, d1);
            d1 = __fmaf_rn(-qz1, p.z, d1);
            bool pr0 = d0 < u0;
            bool pr1 = d1 < u1;
            unsigned m0 = __ballot_sync(0xffffffffu, pr0);
            unsigned m1 = __ballot_sync(0xffffffffu, pr1);
            if (pr0) {
                unsigned ub = mono_map(d0 + c20);
                cb0[c0 + __popc(m0 & lml)] = ((ull)ub << 32) | (unsigned)(t + j);
            }
            if (pr1) {
                unsigned ub = mono_map(d1 + c21);
                cb1[c1 + __popc(m1 & lml)] = ((ull)ub << 32) | (unsigned)(t + j);
            }
            c0 += __popc(m0);
            c1 += __popc(m1);
        }
    }
    knn_flush(top0, c0, thr0, cb0, nt, lane);
    knn_flush(top1, c1, thr1, cb1, nt, lane);
    g_idx[(b*NPT + qg + 0)*NS + lane] = (int)(top0 & 0xffffffffu);
    g_idx[(b*NPT + qg + 1)*NS + lane] = (int)(top1 & 0xffffffffu);
}

// ---------------- layer1: feat(67) @ W1^T + b1 -> g_h1 (pre-BN), 2 rows/thread ----------------
__global__ __launch_bounds__(256) void k_layer1(const float* __restrict__ xyz,
                                                const int* __restrict__ sidx,
                                                const float* __restrict__ W1,
                                                const float* __restrict__ b1) {
    __shared__ float ws[67*64];
    __shared__ float bs[64];
    int tid = threadIdx.x;
    for (int i = tid; i < 67*64; i += 256) {
        int o = i / 67, k = i - o*67;
        ws[k*64 + o] = W1[i];
    }
    if (tid < 64) bs[tid] = b1[tid];
    __syncthreads();
    int row0 = blockIdx.x*512 + tid;
    int row1 = row0 + 256;
    int b = row0 >> 16;
    int p0 = (row0 >> 5) & (NPT-1), p1 = (row1 >> 5) & (NPT-1);
    int n0 = g_idx[row0], n1 = g_idx[row1];
    float4 pa = g_pxyz[b*NN + n0];
    float4 pb = g_pxyz[b*NN + n1];
    int s0 = sidx[p0], s1 = sidx[p1];
    float a0 = pa.x - xyz[(b*3+0)*NN + s0];
    float a1 = pa.y - xyz[(b*3+1)*NN + s0];
    float a2 = pa.z - xyz[(b*3+2)*NN + s0];
    float e0 = pb.x - xyz[(b*3+0)*NN + s1];
    float e1 = pb.y - xyz[(b*3+1)*NN + s1];
    float e2 = pb.z - xyz[(b*3+2)*NN + s1];
    const float4* fa = (const float4*)&g_ptst[((size_t)(b*NN + n0))*64];
    const float4* fb = (const float4*)&g_ptst[((size_t)(b*NN + n1))*64];
    #pragma unroll
    for (int pass = 0; pass < 2; ++pass) {
        const int po = pass*32;
        float acc0[32], acc1[32];
        #pragma unroll
        for (int o = 0; o < 32; ++o) {
            float w0 = ws[po+o], w1 = ws[64+po+o], w2 = ws[128+po+o];
            acc0[o] = bs[po+o] + a0*w0 + a1*w1 + a2*w2;
            acc1[o] = bs[po+o] + e0*w0 + e1*w1 + e2*w2;
        }
        #pragma unroll 4
        for (int k4 = 0; k4 < 16; ++k4) {
            float4 ha = __ldg(&fa[k4]);
            float4 hb = __ldg(&fb[k4]);
            float f0[4] = {ha.x, ha.y, ha.z, ha.w};
            float f1[4] = {hb.x, hb.y, hb.z, hb.w};
            #pragma unroll
            for (int kk = 0; kk < 4; ++kk) {
                const float4* w4 = (const float4*)&ws[(3 + k4*4 + kk)*64 + po];
                #pragma unroll
                for (int o4 = 0; o4 < 8; ++o4) {
                    float4 wv = w4[o4];
                    acc0[o4*4+0] += f0[kk]*wv.x; acc0[o4*4+1] += f0[kk]*wv.y;
                    acc0[o4*4+2] += f0[kk]*wv.z; acc0[o4*4+3] += f0[kk]*wv.w;
                    acc1[o4*4+0] += f1[kk]*wv.x; acc1[o4*4+1] += f1[kk]*wv.y;
                    acc1[o4*4+2] += f1[kk]*wv.z; acc1[o4*4+3] += f1[kk]*wv.w;
                }
            }
        }
        float4* op0 = (float4*)&g_h1[(size_t)row0*64 + po];
        float4* op1 = (float4*)&g_h1[(size_t)row1*64 + po];
        #pragma unroll
        for (int o4 = 0; o4 < 8; ++o4) {
            op0[o4] = make_float4(acc0[o4*4], acc0[o4*4+1], acc0[o4*4+2], acc0[o4*4+3]);
            op1[o4] = make_float4(acc1[o4*4], acc1[o4*4+1], acc1[o4*4+2], acc1[o4*4+3]);
        }
    }
}

// ---------------- layer2/3 body: relu(BN(hin)) @ W^T + b, 2 rows/thread ----------------
template<int OUTSTRIDE>
__device__ __forceinline__ void layer_body(const float* __restrict__ hin_g,
                                           float* __restrict__ hout_g, int ooff,
                                           const float* ws, const float* bs,
                                           const float* sc, const float* sh) {
    size_t row0 = (size_t)blockIdx.x*512 + threadIdx.x;
    size_t row1 = row0 + 256;
    const float4* ha4 = (const float4*)&hin_g[row0*64];
    const float4* hb4 = (const float4*)&hin_g[row1*64];
    #pragma unroll
    for (int pass = 0; pass < 2; ++pass) {
        const int po = pass*32;
        float acc0[32], acc1[32];
        #pragma unroll
        for (int o = 0; o < 32; ++o) { acc0[o] = bs[po+o]; acc1[o] = bs[po+o]; }
        #pragma unroll 4
        for (int k4 = 0; k4 < 16; ++k4) {
            float4 ha = __ldg(&ha4[k4]);
            float4 hb = __ldg(&hb4[k4]);
            float4 s4 = *(const float4*)&sc[k4*4];
            float4 t4 = *(const float4*)&sh[k4*4];
            float f0[4] = { fmaxf(ha.x*s4.x + t4.x, 0.0f), fmaxf(ha.y*s4.y + t4.y, 0.0f),
                            fmaxf(ha.z*s4.z + t4.z, 0.0f), fmaxf(ha.w*s4.w + t4.w, 0.0f) };
            float f1[4] = { fmaxf(hb.x*s4.x + t4.x, 0.0f), fmaxf(hb.y*s4.y + t4.y, 0.0f),
                            fmaxf(hb.z*s4.z + t4.z, 0.0f), fmaxf(hb.w*s4.w + t4.w, 0.0f) };
            #pragma unroll
            for (int kk = 0; kk < 4; ++kk) {
                const float4* w4 = (const float4*)&ws[(k4*4 + kk)*64 + po];
                #pragma unroll
                for (int o4 = 0; o4 < 8; ++o4) {
                    float4 wv = w4[o4];
                    acc0[o4*4+0] += f0[kk]*wv.x; acc0[o4*4+1] += f0[kk]*wv.y;
                    acc0[o4*4+2] += f0[kk]*wv.z; acc0[o4*4+3] += f0[kk]*wv.w;
                    acc1[o4*4+0] += f1[kk]*wv.x; acc1[o4*4+1] += f1[kk]*wv.y;
                    acc1[o4*4+2] += f1[kk]*wv.z; acc1[o4*4+3] += f1[kk]*wv.w;
                }
            }
        }
        float4* op0 = (float4*)&hout_g[row0*OUTSTRIDE + ooff + po];
        float4* op1 = (float4*)&hout_g[row1*OUTSTRIDE + ooff + po];
        #pragma unroll
        for (int o4 = 0; o4 < 8; ++o4) {
            op0[o4] = make_float4(acc0[o4*4], acc0[o4*4+1], acc0[o4*4+2], acc0[o4*4+3]);
            op1[o4] = make_float4(acc1[o4*4], acc1[o4*4+1], acc1[o4*4+2], acc1[o4*4+3]);
        }
    }
}

__global__ __launch_bounds__(256) void k_layer2(const float* __restrict__ W2,
                                                const float* __restrict__ b2,
                                                const float* __restrict__ g1,
                                                const float* __restrict__ be1) {
    __shared__ float ws[64*64];
    __shared__ float bs[64], sc[64], sh[64];
    int tid = threadIdx.x;
    for (int i = tid; i < 64*64; i += 256) {
        int o = i >> 6, k = i & 63;
        ws[k*64 + o] = W2[i];
    }
    if (tid < 64) {
        bs[tid] = b2[tid];
        float m = g_stats[tid] * INV_ROWS;
        float v = g_stats[64+tid] * INV_ROWS - m*m;
        float scv = g1[tid] * rsqrtf(v + EPSV);
        sc[tid] = scv;
        sh[tid] = be1[tid] - m*scv;
    }
    __syncthreads();
    layer_body<64>(g_h1, g_h2, 0, ws, bs, sc, sh);
}

__global__ __launch_bounds__(256) void k_layer3(const float* __restrict__ W3,
                                                const float* __restrict__ b3,
                                                const float* __restrict__ g2,
                                                const float* __restrict__ be2) {
    __shared__ float ws[64*64];
    __shared__ float bs[64], sc[64], sh[64];
    int tid = threadIdx.x;
    int oh = blockIdx.y;
    for (int i = tid; i < 64*64; i += 256) {
        int o = i >> 6, k = i & 63;
        ws[k*64 + o] = W3[(oh*64 + o)*64 + k];
    }
    if (tid < 64) {
        bs[tid] = b3[oh*64 + tid];
        float m = g_stats[128+tid] * INV_ROWS;
        float v = g_stats[192+tid] * INV_ROWS - m*m;
        float scv = g2[tid] * rsqrtf(v + EPSV);
        sc[tid] = scv;
        sh[tid] = be2[tid] - m*scv;
    }
    __syncthreads();
    layer_body<128>(g_h2, g_h3, oh*64, ws, bs, sc, sh);
}

// ---------------- per-channel sum/sumsq reduction (layers 1,2) ----------------
template<int WHICH>
__global__ __launch_bounds__(256) void k_reduce() {
    const float* h = (WHICH == 1) ? g_h1 : g_h2;
    const int soff = (WHICH == 1) ? 0 : 128;
    const int qoff = soff + 64;
    const int G = 16;
    int tid = threadIdx.x;
    int g = tid % G;
    const int rpb = 16;
    size_t r = (size_t)blockIdx.x*rpb + (size_t)(tid / G);
    size_t rstr = (size_t)gridDim.x*rpb;
    float4 s = make_float4(0,0,0,0), q = make_float4(0,0,0,0);
    for (; r < (size_t)ROWS; r += rstr) {
        float4 v = *(const float4*)&h[r*64 + g*4];
        s.x += v.x; s.y += v.y; s.z += v.z; s.w += v.w;
        q.x += v.x*v.x; q.y += v.y*v.y; q.z += v.z*v.z; q.w += v.w*v.w;
    }
    __shared__ float ssum[64], ssq[64];
    if (tid < 64) { ssum[tid] = 0.0f; ssq[tid] = 0.0f; }
    __syncthreads();
    atomicAdd(&ssum[g*4+0], s.x); atomicAdd(&ssum[g*4+1], s.y);
    atomicAdd(&ssum[g*4+2], s.z); atomicAdd(&ssum[g*4+3], s.w);
    atomicAdd(&ssq[g*4+0], q.x);  atomicAdd(&ssq[g*4+1], q.y);
    atomicAdd(&ssq[g*4+2], q.z);  atomicAdd(&ssq[g*4+3], q.w);
    __syncthreads();
    if (tid < 64) {
        atomicAdd(&g_stats[soff + tid], ssum[tid]);
        atomicAdd(&g_stats[qoff + tid], ssq[tid]);
    }
}

// ---------------- pool: one pass over h3: max/min over samples + sum/sumsq stats ----------------
__global__ __launch_bounds__(256) void k_pool() {
    int gi = blockIdx.x*256 + threadIdx.x;     // 524288 threads
    int tid = threadIdx.x;
    int cg = (gi & 31) * 4;
    int bp = gi >> 5;
    const float* base = &g_h3[((size_t)bp*NS)*128 + cg];
    float mxa[4] = {-3.4e38f, -3.4e38f, -3.4e38f, -3.4e38f};
    float mna[4] = { 3.4e38f,  3.4e38f,  3.4e38f,  3.4e38f};
    float sa[4] = {0,0,0,0}, qa[4] = {0,0,0,0};
    #pragma unroll 4
    for (int s = 0; s < NS; ++s) {
        float4 v = *(const float4*)(base + (size_t)s*128);
        mxa[0] = fmaxf(mxa[0], v.x); mna[0] = fminf(mna[0], v.x); sa[0] += v.x; qa[0] += v.x*v.x;
        mxa[1] = fmaxf(mxa[1], v.y); mna[1] = fminf(mna[1], v.y); sa[1] += v.y; qa[1] += v.y*v.y;
        mxa[2] = fmaxf(mxa[2], v.z); mna[2] = fminf(mna[2], v.z); sa[2] += v.z; qa[2] += v.z*v.z;
        mxa[3] = fmaxf(mxa[3], v.w); mna[3] = fminf(mna[3], v.w); sa[3] += v.w; qa[3] += v.w*v.w;
    }
    *(float4*)&g_mx[(size_t)bp*128 + cg] = make_float4(mxa[0], mxa[1], mxa[2], mxa[3]);
    *(float4*)&g_mn[(size_t)bp*128 + cg] = make_float4(mna[0], mna[1], mna[2], mna[3]);
    __shared__ float ssum[128], ssq[128];
    if (tid < 128) { ssum[tid] = 0.0f; ssq[tid] = 0.0f; }
    __syncthreads();
    #pragma unroll
    for (int j = 0; j < 4; ++j) {
        atomicAdd(&ssum[cg+j], sa[j]);
        atomicAdd(&ssq[cg+j], qa[j]);
    }
    __syncthreads();
    if (tid < 128)      atomicAdd(&g_stats[256 + tid], ssum[tid]);
    else                atomicAdd(&g_stats[384 + tid - 128], ssq[tid - 128]);
}

// ---------------- apply BN3 affine to pooled max/min, transpose-store ----------------
__global__ __launch_bounds__(256) void k_apply(const float* __restrict__ g3,
                                               const float* __restrict__ be3,
                                               float* __restrict__ outp) {
    int i = blockIdx.x*256 + threadIdx.x;      // 16384*128
    int c = i & 127;
    int bp = i >> 7;
    int b = bp >> 11, p = bp & (NPT-1);
    float m = g_stats[256+c] * INV_ROWS;
    float v = g_stats[384+c] * INV_ROWS - m*m;
    float scv = g3[c] * rsqrtf(v + EPSV);
    float sh = be3[c] - m*scv;
    float pick = (scv >= 0.0f) ? g_mx[i] : g_mn[i];
    outp[((size_t)b*128 + c)*NPT + p] = pick*scv + sh;
}

// ---------------- launch ----------------
extern "C" void kernel_launch(void* const* d_in, const int* in_sizes, int n_in,
                              void* d_out, int out_size) {
    const float* xyz    = (const float*)d_in[0];
    const float* points = (const float*)d_in[1];
    const int*   sidx   = (const int*)d_in[2];
    const float* W1 = (const float*)d_in[3];
    const float* b1 = (const float*)d_in[4];
    const float* g1 = (const float*)d_in[5];
    const float* be1 = (const float*)d_in[6];
    const float* W2 = (const float*)d_in[7];
    const float* b2 = (const float*)d_in[8];
    const float* g2 = (const float*)d_in[9];
    const float* be2 = (const float*)d_in[10];
    const float* W3 = (const float*)d_in[11];
    const float* b3 = (const float*)d_in[12];
    const float* g3 = (const float*)d_in[13];
    const float* be3 = (const float*)d_in[14];

    float* outq = (float*)d_out;                 // (B,3,NPT)
    float* outp = outq + (size_t)BB*3*NPT;       // (B,128,NPT)

    k_prep<<<(BB*NN + 255)/256, 256>>>(xyz);
    k_transpose<<<(BB*NN*16 + 255)/256, 256>>>(points);
    k_gatherq<<<(BB*3*NPT + 255)/256, 256>>>(xyz, sidx, outq);
    k_knn<<<dim3(NPT/16, BB), 256>>>(xyz, sidx);
    k_layer1<<<ROWS/512, 256>>>(xyz, sidx, W1, b1);
    k_reduce<1><<<2048, 256>>>();
    k_layer2<<<ROWS/512, 256>>>(W2, b2, g1, be1);
    k_reduce<2><<<2048, 256>>>();
    k_layer3<<<dim3(ROWS/512, 2), 256>>>(W3, b3, g2, be2);
    k_pool<<<ROWS/256, 256>>>();
    k_apply<<<(BB*NPT*128)/256, 256>>>(g3, be3, outp);
}

// round 4
// speedup vs baseline: 1.5197x; 1.0396x over previous
#include <cuda_runtime.h>

#define BB 8
#define NN 16384
#define NPT 2048
#define NS 32
#define ROWS (BB*NPT*NS)   /* 524288 */
#define EPSV 1e-5f
#define INV_ROWS (1.0f/524288.0f)
#define BPAD 68

typedef unsigned long long ull;
typedef unsigned int u32;

// ---------------- static device scratch ----------------
__device__ float4 g_pxyz[BB*NN];                       // packed (x,y,z,0.5*|p|^2)
__device__ float  g_ptst[(size_t)BB*NN*64];            // points transposed [b][n][c]
__device__ int    g_idx[BB*NPT*NS];                    // knn indices
__device__ float  g_h1[(size_t)ROWS*64];               // pre-BN layer1 out
__device__ float  g_h2[(size_t)ROWS*64];               // pre-BN layer2 out
__device__ float  g_h3[(size_t)ROWS*128];              // pre-BN layer3 out
__device__ float  g_mx[BB*NPT*128];                    // pre-BN pooled max
__device__ float  g_mn[BB*NPT*128];                    // pre-BN pooled min
__device__ float  g_stats[512];                        // S1 Q1 S2 Q2 S3[128] Q3[128]

// ---------------- tf32 helpers ----------------
__device__ __forceinline__ u32 f2tf32(float f) {
    u32 r;
    asm("cvt.rna.tf32.f32 %0, %1;" : "=r"(r) : "f"(f));
    return r;
}
__device__ __forceinline__ void tf32_split(float f, u32& hi, u32& lo) {
    hi = f2tf32(f);
    lo = f2tf32(f - __uint_as_float(hi));
}
__device__ __forceinline__ void mma_tf32(float& d0, float& d1, float& d2, float& d3,
                                         u32 a0, u32 a1, u32 a2, u32 a3,
                                         u32 b0, u32 b1) {
    asm volatile(
        "mma.sync.aligned.m16n8k8.row.col.f32.tf32.tf32.f32 "
        "{%0,%1,%2,%3}, {%4,%5,%6,%7}, {%8,%9}, {%0,%1,%2,%3};\n"
        : "+f"(d0), "+f"(d1), "+f"(d2), "+f"(d3)
        : "r"(a0), "r"(a1), "r"(a2), "r"(a3), "r"(b0), "r"(b1));
}

// ---------------- prep: zero stats + pack xyz with 0.5*|p|^2 ----------------
__global__ void k_prep(const float* __restrict__ xyz) {
    int i = blockIdx.x*256 + threadIdx.x;
    if (i < 512) g_stats[i] = 0.0f;
    if (i >= BB*NN) return;
    int b = i >> 14, n = i & (NN-1);
    float x = xyz[(b*3+0)*NN + n];
    float y = xyz[(b*3+1)*NN + n];
    float z = xyz[(b*3+2)*NN + n];
    g_pxyz[i] = make_float4(x, y, z, 0.5f*(x*x + y*y + z*z));
}

// ---------------- transpose points (B,C,N) -> (B,N,C) ----------------
__global__ void k_transpose(const float* __restrict__ pts) {
    int i = blockIdx.x*256 + threadIdx.x;
    if (i >= BB*NN*16) return;
    int cg = (i & 15) * 4;
    int bn = i >> 4;
    int b = bn >> 14, n = bn & (NN-1);
    const float* src = pts + ((size_t)(b*64 + cg))*NN + n;
    float4 v = make_float4(src[0], src[NN], src[2*NN], src[3*NN]);
    *(float4*)&g_ptst[(size_t)bn*64 + cg] = v;
}

// ---------------- output part 1: gathered centroids (B,3,NPT) ----------------
__global__ void k_gatherq(const float* __restrict__ xyz, const int* __restrict__ sidx,
                          float* __restrict__ outq) {
    int i = blockIdx.x*256 + threadIdx.x;
    if (i >= BB*3*NPT) return;
    int p = i & (NPT-1);
    int bc = i >> 11;
    outq[i] = xyz[bc*NN + sidx[p]];
}

// ---------------- knn flush: merge <=64 buffered candidates into sorted top-32 ----------------
__device__ __forceinline__ void knn_flush(ull& top, int& cnt, float& thr,
                                          ull* cb, ull* nt, int lane) {
    const ull INFK = ~0ull;
    ull e1 = (lane      < cnt) ? cb[lane]      : INFK;
    ull e2 = (lane + 32 < cnt) ? cb[lane + 32] : INFK;
    int r0 = 0, r1 = 0, r2 = 0;
    #pragma unroll 8
    for (int j = 0; j < 32; ++j) {
        ull kj = __shfl_sync(0xffffffffu, top, j);
        r0 += (kj < top); r1 += (kj < e1); r2 += (kj < e2);
    }
    #pragma unroll 8
    for (int j = 0; j < 64; ++j) {
        ull kj = (j < cnt) ? cb[j] : INFK;
        r0 += (kj < top); r1 += (kj < e1); r2 += (kj < e2);
    }
    nt[lane] = INFK;
    __syncwarp();
    if (top != INFK && r0 < 32) nt[r0] = top;
    if (e1  != INFK && r1 < 32) nt[r1] = e1;
    if (e2  != INFK && r2 < 32) nt[r2] = e2;
    __syncwarp();
    top = nt[lane];
    cnt = 0;
    ull k31 = __shfl_sync(0xffffffffu, top, 31);
    unsigned u = (unsigned)(k31 >> 32);
    float t;
    if (u == 0xFFFFFFFFu) {
        t = __int_as_float(0x7F800000);  // +inf
    } else {
        unsigned bits = (u & 0x80000000u) ? (u & 0x7FFFFFFFu) : ~u;
        t = __uint_as_float(bits);
    }
    thr = t;
    __syncwarp();
}

__device__ __forceinline__ unsigned mono_map(float v) {
    unsigned u = __float_as_uint(v);
    return (u & 0x80000000u) ? ~u : (u | 0x80000000u);
}

// ---------------- knn: 16 queries/block (2 per warp), smem point tiles ----------------
__global__ __launch_bounds__(256) void k_knn(const float* __restrict__ xyz,
                                             const int* __restrict__ sidx) {
    __shared__ float4 sp[1024];                       // 16KB
    __shared__ ull cbuf[16*64];                       // 8KB
    __shared__ ull ntop[8*32];                        // 2KB
    int tid = threadIdx.x, lane = tid & 31, w = tid >> 5;
    int b = blockIdx.y;
    unsigned lml = (1u << lane) - 1u;
    ull* cb0 = &cbuf[(w*2+0)*64];
    ull* cb1 = &cbuf[(w*2+1)*64];
    ull* nt = &ntop[w*32];

    int qg = blockIdx.x*16 + w*2;
    int s0 = sidx[qg], s1 = sidx[qg+1];
    float qx0 = xyz[(b*3+0)*NN + s0], qy0 = xyz[(b*3+1)*NN + s0], qz0 = xyz[(b*3+2)*NN + s0];
    float qx1 = xyz[(b*3+0)*NN + s1], qy1 = xyz[(b*3+1)*NN + s1], qz1 = xyz[(b*3+2)*NN + s1];
    float c20 = 0.5f*(qx0*qx0 + qy0*qy0 + qz0*qz0);
    float c21 = 0.5f*(qx1*qx1 + qy1*qy1 + qz1*qz1);
    const float INFF = __int_as_float(0x7F800000);
    ull top0 = ~0ull, top1 = ~0ull;
    float thr0 = INFF, thr1 = INFF;
    float u0 = INFF, u1 = INFF;
    int c0 = 0, c1 = 0;

    for (int t = 0; t < NN; t += 1024) {
        __syncthreads();
        #pragma unroll
        for (int j = 0; j < 4; ++j)
            sp[tid + j*256] = g_pxyz[b*NN + t + tid + j*256];
        __syncthreads();
        for (int j = lane; j < 1024; j += 32) {
            if ((c0 | c1) > 32) {      // warp-uniform, rare
                if (c0 > 32) { knn_flush(top0, c0, thr0, cb0, nt, lane); u0 = thr0 - c20; }
                if (c1 > 32) { knn_flush(top1, c1, thr1, cb1, nt, lane); u1 = thr1 - c21; }
            }
            float4 p = sp[j];
            float d0 = __fmaf_rn(-qx0, p.x, p.w);
            d0 = __fmaf_rn(-qy0, p.y, d0);
            d0 = __fmaf_rn(-qz0, p.z, d0);
            float d1 = __fmaf_rn(-qx1, p.x, p.w);
            d1 = __fmaf_rn(-qy1, p.y, d1);
            d1 = __fmaf_rn(-qz1, p.z, d1);
            bool pr0 = d0 < u0;
            bool pr1 = d1 < u1;
            if (__any_sync(0xffffffffu, pr0 || pr1)) {    // fast-skip common case
                unsigned m0 = __ballot_sync(0xffffffffu, pr0);
                unsigned m1 = __ballot_sync(0xffffffffu, pr1);
                if (pr0) {
                    unsigned ub = mono_map(d0 + c20);
                    cb0[c0 + __popc(m0 & lml)] = ((ull)ub << 32) | (unsigned)(t + j);
                }
                if (pr1) {
                    unsigned ub = mono_map(d1 + c21);
                    cb1[c1 + __popc(m1 & lml)] = ((ull)ub << 32) | (unsigned)(t + j);
                }
                c0 += __popc(m0);
                c1 += __popc(m1);
            }
        }
    }
    knn_flush(top0, c0, thr0, cb0, nt, lane);
    knn_flush(top1, c1, thr1, cb1, nt, lane);
    g_idx[(b*NPT + qg + 0)*NS + lane] = (int)(top0 & 0xffffffffu);
    g_idx[(b*NPT + qg + 1)*NS + lane] = (int)(top1 & 0xffffffffu);
}

// ============================================================================
// Layer kernels: split-TF32 mma.sync.m16n8k8 (A_hi*B_hi + A_hi*B_lo + A_lo*B_hi)
// Block = 256 threads = 8 warps; tile = 128 rows. Each warp: 16 rows x N cols.
// ============================================================================

// ---------------- layer1: feat(72 padded) @ W1^T + b1 -> g_h1 ----------------
// feature order: [gpts(64), relx, rely, relz, 0 x5]; W1 staged to match.
__global__ __launch_bounds__(256) void k_layer1(const float* __restrict__ xyz,
                                                const int* __restrict__ sidx,
                                                const float* __restrict__ W1,
                                                const float* __restrict__ b1) {
    __shared__ u32 bhs[72*BPAD];
    __shared__ u32 bls[72*BPAD];
    __shared__ float bs[64];
    int tid = threadIdx.x;
    for (int i = tid; i < 72*64; i += 256) {
        int k = i >> 6, n = i & 63;
        float wv = 0.0f;
        if (k < 64)       wv = W1[n*67 + 3 + k];
        else if (k < 67)  wv = W1[n*67 + (k - 64)];
        u32 hi, lo; tf32_split(wv, hi, lo);
        bhs[k*BPAD + n] = hi;
        bls[k*BPAD + n] = lo;
    }
    if (tid < 64) bs[tid] = b1[tid];
    __syncthreads();

    int lane = tid & 31, w = tid >> 5;
    int g = lane >> 2, c = lane & 3;
    int row0 = blockIdx.x*128 + w*16 + g;
    int row1 = row0 + 8;
    int b = row0 >> 16;
    int n0 = g_idx[row0], n1 = g_idx[row1];
    int p0 = (row0 >> 5) & (NPT-1);
    int s = sidx[p0];
    float qx = xyz[(b*3+0)*NN + s], qy = xyz[(b*3+1)*NN + s], qz = xyz[(b*3+2)*NN + s];
    float4 P0 = g_pxyz[b*NN + n0];
    float4 P1 = g_pxyz[b*NN + n1];
    float rel0x = P0.x - qx, rel0y = P0.y - qy, rel0z = P0.z - qz;
    float rel1x = P1.x - qx, rel1y = P1.y - qy, rel1z = P1.z - qz;
    const float* f0 = &g_ptst[(size_t)(b*NN + n0)*64];
    const float* f1 = &g_ptst[(size_t)(b*NN + n1)*64];

    u32 ah[9][4], al[9][4];
    #pragma unroll
    for (int t = 0; t < 16; ++t) {
        int col = c + 4*t;
        float x0 = __ldg(&f0[col]);
        float x1 = __ldg(&f1[col]);
        int k = t >> 1, sl = (t & 1)*2;
        tf32_split(x0, ah[k][sl],   al[k][sl]);
        tf32_split(x1, ah[k][sl+1], al[k][sl+1]);
    }
    {   // k-step 8: cols 64..71 -> rel / zero-pad
        float e0 = (c == 0) ? rel0x : (c == 1) ? rel0y : (c == 2) ? rel0z : 0.0f;
        float e1 = (c == 0) ? rel1x : (c == 1) ? rel1y : (c == 2) ? rel1z : 0.0f;
        tf32_split(e0, ah[8][0], al[8][0]);
        tf32_split(e1, ah[8][1], al[8][1]);
        ah[8][2] = 0; al[8][2] = 0;
        ah[8][3] = 0; al[8][3] = 0;
    }

    const u32* bhp = &bhs[c*BPAD + g];
    const u32* blp = &bls[c*BPAD + g];
    #pragma unroll
    for (int n8 = 0; n8 < 8; ++n8) {
        float d0 = bs[n8*8 + 2*c], d1 = bs[n8*8 + 2*c + 1];
        float d2 = d0, d3 = d1;
        #pragma unroll
        for (int k = 0; k < 9; ++k) {
            int off = k*8*BPAD + n8*8;
            u32 b0h = bhp[off], b1h = bhp[off + 4*BPAD];
            u32 b0l = blp[off], b1l = blp[off + 4*BPAD];
            mma_tf32(d0,d1,d2,d3, ah[k][0],ah[k][1],ah[k][2],ah[k][3], b0h,b1h);
            mma_tf32(d0,d1,d2,d3, ah[k][0],ah[k][1],ah[k][2],ah[k][3], b0l,b1l);
            mma_tf32(d0,d1,d2,d3, al[k][0],al[k][1],al[k][2],al[k][3], b0h,b1h);
        }
        *(float2*)&g_h1[(size_t)row0*64 + n8*8 + 2*c] = make_float2(d0, d1);
        *(float2*)&g_h1[(size_t)row1*64 + n8*8 + 2*c] = make_float2(d2, d3);
    }
}

// ---------------- layer2: relu(BN1(h1)) @ W2^T + b2 -> g_h2 ----------------
__global__ __launch_bounds__(256) void k_layer2(const float* __restrict__ W2,
                                                const float* __restrict__ b2,
                                                const float* __restrict__ g1,
                                                const float* __restrict__ be1) {
    __shared__ u32 bhs[64*BPAD];
    __shared__ u32 bls[64*BPAD];
    __shared__ float bs[64], sc[64], sh[64];
    int tid = threadIdx.x;
    for (int i = tid; i < 64*64; i += 256) {
        int k = i >> 6, n = i & 63;
        float wv = W2[n*64 + k];
        u32 hi, lo; tf32_split(wv, hi, lo);
        bhs[k*BPAD + n] = hi;
        bls[k*BPAD + n] = lo;
    }
    if (tid < 64) {
        bs[tid] = b2[tid];
        float m = g_stats[tid] * INV_ROWS;
        float v = g_stats[64+tid] * INV_ROWS - m*m;
        float scv = g1[tid] * rsqrtf(v + EPSV);
        sc[tid] = scv;
        sh[tid] = be1[tid] - m*scv;
    }
    __syncthreads();

    int lane = tid & 31, w = tid >> 5;
    int g = lane >> 2, c = lane & 3;
    size_t row0 = (size_t)blockIdx.x*128 + w*16 + g;
    size_t row1 = row0 + 8;
    const float* h0 = &g_h1[row0*64];
    const float* h1p = &g_h1[row1*64];

    u32 ah[8][4], al[8][4];
    #pragma unroll
    for (int t = 0; t < 16; ++t) {
        int col = c + 4*t;
        float scv = sc[col], shv = sh[col];
        float x0 = fmaxf(__ldg(&h0[col]) * scv + shv, 0.0f);
        float x1 = fmaxf(__ldg(&h1p[col]) * scv + shv, 0.0f);
        int k = t >> 1, sl = (t & 1)*2;
        tf32_split(x0, ah[k][sl],   al[k][sl]);
        tf32_split(x1, ah[k][sl+1], al[k][sl+1]);
    }

    const u32* bhp = &bhs[c*BPAD + g];
    const u32* blp = &bls[c*BPAD + g];
    #pragma unroll
    for (int n8 = 0; n8 < 8; ++n8) {
        float d0 = bs[n8*8 + 2*c], d1 = bs[n8*8 + 2*c + 1];
        float d2 = d0, d3 = d1;
        #pragma unroll
        for (int k = 0; k < 8; ++k) {
            int off = k*8*BPAD + n8*8;
            u32 b0h = bhp[off], b1h = bhp[off + 4*BPAD];
            u32 b0l = blp[off], b1l = blp[off + 4*BPAD];
            mma_tf32(d0,d1,d2,d3, ah[k][0],ah[k][1],ah[k][2],ah[k][3], b0h,b1h);
            mma_tf32(d0,d1,d2,d3, ah[k][0],ah[k][1],ah[k][2],ah[k][3], b0l,b1l);
            mma_tf32(d0,d1,d2,d3, al[k][0],al[k][1],al[k][2],al[k][3], b0h,b1h);
        }
        *(float2*)&g_h2[row0*64 + n8*8 + 2*c] = make_float2(d0, d1);
        *(float2*)&g_h2[row1*64 + n8*8 + 2*c] = make_float2(d2, d3);
    }
}

// ---------------- layer3 (half per blockIdx.y): relu(BN2(h2)) @ W3^T + b3 -> g_h3 ----------------
__global__ __launch_bounds__(256) void k_layer3(const float* __restrict__ W3,
                                                const float* __restrict__ b3,
                                                const float* __restrict__ g2,
                                                const float* __restrict__ be2) {
    __shared__ u32 bhs[64*BPAD];
    __shared__ u32 bls[64*BPAD];
    __shared__ float bs[64], sc[64], sh[64];
    int tid = threadIdx.x;
    int oh = blockIdx.y;
    for (int i = tid; i < 64*64; i += 256) {
        int k = i >> 6, n = i & 63;
        float wv = W3[(oh*64 + n)*64 + k];
        u32 hi, lo; tf32_split(wv, hi, lo);
        bhs[k*BPAD + n] = hi;
        bls[k*BPAD + n] = lo;
    }
    if (tid < 64) {
        bs[tid] = b3[oh*64 + tid];
        float m = g_stats[128+tid] * INV_ROWS;
        float v = g_stats[192+tid] * INV_ROWS - m*m;
        float scv = g2[tid] * rsqrtf(v + EPSV);
        sc[tid] = scv;
        sh[tid] = be2[tid] - m*scv;
    }
    __syncthreads();

    int lane = tid & 31, w = tid >> 5;
    int g = lane >> 2, c = lane & 3;
    size_t row0 = (size_t)blockIdx.x*128 + w*16 + g;
    size_t row1 = row0 + 8;
    const float* h0 = &g_h2[row0*64];
    const float* h1p = &g_h2[row1*64];

    u32 ah[8][4], al[8][4];
    #pragma unroll
    for (int t = 0; t < 16; ++t) {
        int col = c + 4*t;
        float scv = sc[col], shv = sh[col];
        float x0 = fmaxf(__ldg(&h0[col]) * scv + shv, 0.0f);
        float x1 = fmaxf(__ldg(&h1p[col]) * scv + shv, 0.0f);
        int k = t >> 1, sl = (t & 1)*2;
        tf32_split(x0, ah[k][sl],   al[k][sl]);
        tf32_split(x1, ah[k][sl+1], al[k][sl+1]);
    }

    const u32* bhp = &bhs[c*BPAD + g];
    const u32* blp = &bls[c*BPAD + g];
    #pragma unroll
    for (int n8 = 0; n8 < 8; ++n8) {
        float d0 = bs[n8*8 + 2*c], d1 = bs[n8*8 + 2*c + 1];
        float d2 = d0, d3 = d1;
        #pragma unroll
        for (int k = 0; k < 8; ++k) {
            int off = k*8*BPAD + n8*8;
            u32 b0h = bhp[off], b1h = bhp[off + 4*BPAD];
            u32 b0l = blp[off], b1l = blp[off + 4*BPAD];
            mma_tf32(d0,d1,d2,d3, ah[k][0],ah[k][1],ah[k][2],ah[k][3], b0h,b1h);
            mma_tf32(d0,d1,d2,d3, ah[k][0],ah[k][1],ah[k][2],ah[k][3], b0l,b1l);
            mma_tf32(d0,d1,d2,d3, al[k][0],al[k][1],al[k][2],al[k][3], b0h,b1h);
        }
        *(float2*)&g_h3[row0*128 + oh*64 + n8*8 + 2*c] = make_float2(d0, d1);
        *(float2*)&g_h3[row1*128 + oh*64 + n8*8 + 2*c] = make_float2(d2, d3);
    }
}

// ---------------- per-channel sum/sumsq reduction (layers 1,2) ----------------
template<int WHICH>
__global__ __launch_bounds__(256) void k_reduce() {
    const float* h = (WHICH == 1) ? g_h1 : g_h2;
    const int soff = (WHICH == 1) ? 0 : 128;
    const int qoff = soff + 64;
    const int G = 16;
    int tid = threadIdx.x;
    int g = tid % G;
    const int rpb = 16;
    size_t r = (size_t)blockIdx.x*rpb + (size_t)(tid / G);
    size_t rstr = (size_t)gridDim.x*rpb;
    float4 s = make_float4(0,0,0,0), q = make_float4(0,0,0,0);
    for (; r < (size_t)ROWS; r += rstr) {
        float4 v = *(const float4*)&h[r*64 + g*4];
        s.x += v.x; s.y += v.y; s.z += v.z; s.w += v.w;
        q.x += v.x*v.x; q.y += v.y*v.y; q.z += v.z*v.z; q.w += v.w*v.w;
    }
    __shared__ float ssum[64], ssq[64];
    if (tid < 64) { ssum[tid] = 0.0f; ssq[tid] = 0.0f; }
    __syncthreads();
    atomicAdd(&ssum[g*4+0], s.x); atomicAdd(&ssum[g*4+1], s.y);
    atomicAdd(&ssum[g*4+2], s.z); atomicAdd(&ssum[g*4+3], s.w);
    atomicAdd(&ssq[g*4+0], q.x);  atomicAdd(&ssq[g*4+1], q.y);
    atomicAdd(&ssq[g*4+2], q.z);  atomicAdd(&ssq[g*4+3], q.w);
    __syncthreads();
    if (tid < 64) {
        atomicAdd(&g_stats[soff + tid], ssum[tid]);
        atomicAdd(&g_stats[qoff + tid], ssq[tid]);
    }
}

// ---------------- pool: one pass over h3: max/min over samples + sum/sumsq stats ----------------
__global__ __launch_bounds__(256) void k_pool() {
    int gi = blockIdx.x*256 + threadIdx.x;     // 524288 threads
    int tid = threadIdx.x;
    int cg = (gi & 31) * 4;
    int bp = gi >> 5;
    const float* base = &g_h3[((size_t)bp*NS)*128 + cg];
    float mxa[4] = {-3.4e38f, -3.4e38f, -3.4e38f, -3.4e38f};
    float mna[4] = { 3.4e38f,  3.4e38f,  3.4e38f,  3.4e38f};
    float sa[4] = {0,0,0,0}, qa[4] = {0,0,0,0};
    #pragma unroll 4
    for (int s = 0; s < NS; ++s) {
        float4 v = *(const float4*)(base + (size_t)s*128);
        mxa[0] = fmaxf(mxa[0], v.x); mna[0] = fminf(mna[0], v.x); sa[0] += v.x; qa[0] += v.x*v.x;
        mxa[1] = fmaxf(mxa[1], v.y); mna[1] = fminf(mna[1], v.y); sa[1] += v.y; qa[1] += v.y*v.y;
        mxa[2] = fmaxf(mxa[2], v.z); mna[2] = fminf(mna[2], v.z); sa[2] += v.z; qa[2] += v.z*v.z;
        mxa[3] = fmaxf(mxa[3], v.w); mna[3] = fminf(mna[3], v.w); sa[3] += v.w; qa[3] += v.w*v.w;
    }
    *(float4*)&g_mx[(size_t)bp*128 + cg] = make_float4(mxa[0], mxa[1], mxa[2], mxa[3]);
    *(float4*)&g_mn[(size_t)bp*128 + cg] = make_float4(mna[0], mna[1], mna[2], mna[3]);
    __shared__ float ssum[128], ssq[128];
    if (tid < 128) { ssum[tid] = 0.0f; ssq[tid] = 0.0f; }
    __syncthreads();
    #pragma unroll
    for (int j = 0; j < 4; ++j) {
        atomicAdd(&ssum[cg+j], sa[j]);
        atomicAdd(&ssq[cg+j], qa[j]);
    }
    __syncthreads();
    if (tid < 128)      atomicAdd(&g_stats[256 + tid], ssum[tid]);
    else                atomicAdd(&g_stats[384 + tid - 128], ssq[tid - 128]);
}

// ---------------- apply BN3 affine to pooled max/min, transpose-store ----------------
__global__ __launch_bounds__(256) void k_apply(const float* __restrict__ g3,
                                               const float* __restrict__ be3,
                                               float* __restrict__ outp) {
    int i = blockIdx.x*256 + threadIdx.x;      // 16384*128
    int c = i & 127;
    int bp = i >> 7;
    int b = bp >> 11, p = bp & (NPT-1);
    float m = g_stats[256+c] * INV_ROWS;
    float v = g_stats[384+c] * INV_ROWS - m*m;
    float scv = g3[c] * rsqrtf(v + EPSV);
    float sh = be3[c] - m*scv;
    float pick = (scv >= 0.0f) ? g_mx[i] : g_mn[i];
    outp[((size_t)b*128 + c)*NPT + p] = pick*scv + sh;
}

// ---------------- launch ----------------
extern "C" void kernel_launch(void* const* d_in, const int* in_sizes, int n_in,
                              void* d_out, int out_size) {
    const float* xyz    = (const float*)d_in[0];
    const float* points = (const float*)d_in[1];
    const int*   sidx   = (const int*)d_in[2];
    const float* W1 = (const float*)d_in[3];
    const float* b1 = (const float*)d_in[4];
    const float* g1 = (const float*)d_in[5];
    const float* be1 = (const float*)d_in[6];
    const float* W2 = (const float*)d_in[7];
    const float* b2 = (const float*)d_in[8];
    const float* g2 = (const float*)d_in[9];
    const float* be2 = (const float*)d_in[10];
    const float* W3 = (const float*)d_in[11];
    const float* b3 = (const float*)d_in[12];
    const float* g3 = (const float*)d_in[13];
    const float* be3 = (const float*)d_in[14];

    float* outq = (float*)d_out;                 // (B,3,NPT)
    float* outp = outq + (size_t)BB*3*NPT;       // (B,128,NPT)

    k_prep<<<(BB*NN + 255)/256, 256>>>(xyz);
    k_transpose<<<(BB*NN*16 + 255)/256, 256>>>(points);
    k_gatherq<<<(BB*3*NPT + 255)/256, 256>>>(xyz, sidx, outq);
    k_knn<<<dim3(NPT/16, BB), 256>>>(xyz, sidx);
    k_layer1<<<ROWS/128, 256>>>(xyz, sidx, W1, b1);
    k_reduce<1><<<2048, 256>>>();
    k_layer2<<<ROWS/128, 256>>>(W2, b2, g1, be1);
    k_reduce<2><<<2048, 256>>>();
    k_layer3<<<dim3(ROWS/128, 2), 256>>>(W3, b3, g2, be2);
    k_pool<<<ROWS/256, 256>>>();
    k_apply<<<(BB*NPT*128)/256, 256>>>(g3, be3, outp);
}

// round 5
// speedup vs baseline: 2.0102x; 1.3228x over previous
#include <cuda_runtime.h>

#define BB 8
#define NN 16384
#define NPT 2048
#define NS 32
#define ROWS (BB*NPT*NS)   /* 524288 */
#define EPSV 1e-5f
#define INV_ROWS (1.0f/524288.0f)
#define BPAD 72

typedef unsigned long long ull;
typedef unsigned int u32;

// ---------------- static device scratch ----------------
__device__ float4 g_pxyz[BB*NN];                       // packed (x,y,z,0.5*|p|^2)
__device__ float  g_ptst[(size_t)BB*NN*64];            // points transposed [b][n][c]
__device__ int    g_idx[BB*NPT*NS];                    // knn indices
__device__ float  g_h1[(size_t)ROWS*64];               // pre-BN layer1 out
__device__ float  g_h2[(size_t)ROWS*64];               // pre-BN layer2 out
__device__ float  g_mx[BB*NPT*128];                    // pre-BN pooled max
__device__ float  g_mn[BB*NPT*128];                    // pre-BN pooled min
__device__ float  g_stats[512];                        // S1 Q1 S2 Q2 S3[128] Q3[128]
__device__ u32    g_w1h[72*64], g_w1l[72*64];          // pre-split tf32 weights [k][n]
__device__ u32    g_w2h[64*64], g_w2l[64*64];
__device__ u32    g_w3h[64*128], g_w3l[64*128];

// ---------------- tf32 helpers ----------------
__device__ __forceinline__ u32 f2tf32(float f) {
    u32 r;
    asm("cvt.rna.tf32.f32 %0, %1;" : "=r"(r) : "f"(f));
    return r;
}
__device__ __forceinline__ void tf32_split(float f, u32& hi, u32& lo) {
    hi = f2tf32(f);
    lo = f2tf32(f - __uint_as_float(hi));
}
__device__ __forceinline__ void mma_tf32(float& d0, float& d1, float& d2, float& d3,
                                         u32 a0, u32 a1, u32 a2, u32 a3,
                                         u32 b0, u32 b1) {
    asm volatile(
        "mma.sync.aligned.m16n8k8.row.col.f32.tf32.tf32.f32 "
        "{%0,%1,%2,%3}, {%4,%5,%6,%7}, {%8,%9}, {%0,%1,%2,%3};\n"
        : "+f"(d0), "+f"(d1), "+f"(d2), "+f"(d3)
        : "r"(a0), "r"(a1), "r"(a2), "r"(a3), "r"(b0), "r"(b1));
}

// ---------------- prep: stats zero + pxyz pack + gatherq + transpose + weight split ----
#define PREP_XPOSE (BB*NN*16)                          /* 2097152 */
__global__ void k_prep(const float* __restrict__ xyz, const float* __restrict__ pts,
                       const int* __restrict__ sidx,
                       const float* __restrict__ W1, const float* __restrict__ W2,
                       const float* __restrict__ W3, float* __restrict__ outq) {
    int i = blockIdx.x*256 + threadIdx.x;
    if (i < 512) g_stats[i] = 0.0f;
    if (i < BB*NN) {
        int b = i >> 14, n = i & (NN-1);
        float x = xyz[(b*3+0)*NN + n];
        float y = xyz[(b*3+1)*NN + n];
        float z = xyz[(b*3+2)*NN + n];
        g_pxyz[i] = make_float4(x, y, z, 0.5f*(x*x + y*y + z*z));
    }
    if (i < BB*3*NPT) {
        int p = i & (NPT-1);
        int bc = i >> 11;
        outq[i] = xyz[bc*NN + sidx[p]];
    }
    if (i < PREP_XPOSE) {
        int cg = (i & 15) * 4;
        int bn = i >> 4;
        int b = bn >> 14, n = bn & (NN-1);
        const float* src = pts + ((size_t)(b*64 + cg))*NN + n;
        float4 v = make_float4(src[0], src[NN], src[2*NN], src[3*NN]);
        *(float4*)&g_ptst[(size_t)bn*64 + cg] = v;
    } else {
        int wi = i - PREP_XPOSE;
        if (wi < 72*64) {
            int k = wi >> 6, n = wi & 63;
            float wv = 0.0f;
            if (k < 64)      wv = W1[n*67 + 3 + k];
            else if (k < 67) wv = W1[n*67 + (k - 64)];
            u32 hi, lo; tf32_split(wv, hi, lo);
            g_w1h[wi] = hi; g_w1l[wi] = lo;
        } else if (wi < 72*64 + 4096) {
            int j = wi - 72*64;
            int k = j >> 6, n = j & 63;
            u32 hi, lo; tf32_split(W2[n*64 + k], hi, lo);
            g_w2h[j] = hi; g_w2l[j] = lo;
        } else if (wi < 72*64 + 4096 + 8192) {
            int j = wi - 72*64 - 4096;
            int k = j >> 7, n = j & 127;
            u32 hi, lo; tf32_split(W3[n*64 + k], hi, lo);
            g_w3h[j] = hi; g_w3l[j] = lo;
        }
    }
}

// ---------------- knn flush: merge <=128 buffered candidates into sorted top-32 ----
__device__ __forceinline__ void knn_flush(ull& top, int& cnt, float& thr,
                                          ull* cb, ull* nt, int lane) {
    const ull INFK = ~0ull;
    ull e0 = (lane      < cnt) ? cb[lane]      : INFK;
    ull e1 = (lane + 32 < cnt) ? cb[lane + 32] : INFK;
    ull e2 = (lane + 64 < cnt) ? cb[lane + 64] : INFK;
    ull e3 = (lane + 96 < cnt) ? cb[lane + 96] : INFK;
    int r0 = 0, r1 = 0, r2 = 0, r3 = 0, r4 = 0;
    #pragma unroll 8
    for (int j = 0; j < 32; ++j) {
        ull kj = __shfl_sync(0xffffffffu, top, j);
        r0 += (kj < top); r1 += (kj < e0); r2 += (kj < e1);
        r3 += (kj < e2); r4 += (kj < e3);
    }
    for (int j = 0; j < cnt; ++j) {
        ull kj = cb[j];
        r0 += (kj < top); r1 += (kj < e0); r2 += (kj < e1);
        r3 += (kj < e2); r4 += (kj < e3);
    }
    nt[lane] = INFK;
    __syncwarp();
    if (top != INFK && r0 < 32) nt[r0] = top;
    if (e0  != INFK && r1 < 32) nt[r1] = e0;
    if (e1  != INFK && r2 < 32) nt[r2] = e1;
    if (e2  != INFK && r3 < 32) nt[r3] = e2;
    if (e3  != INFK && r4 < 32) nt[r4] = e3;
    __syncwarp();
    top = nt[lane];
    cnt = 0;
    ull k31 = __shfl_sync(0xffffffffu, top, 31);
    unsigned u = (unsigned)(k31 >> 32);
    float t;
    if (u == 0xFFFFFFFFu) {
        t = __int_as_float(0x7F800000);  // +inf
    } else {
        unsigned bits = (u & 0x80000000u) ? (u & 0x7FFFFFFFu) : ~u;
        t = __uint_as_float(bits);
    }
    thr = t;
    __syncwarp();
}

__device__ __forceinline__ unsigned mono_map(float v) {
    unsigned u = __float_as_uint(v);
    return (u & 0x80000000u) ? ~u : (u | 0x80000000u);
}

// ---------------- knn: 16 queries/block (2 per warp), smem point tiles ----------------
__global__ __launch_bounds__(256) void k_knn(const float* __restrict__ xyz,
                                             const int* __restrict__ sidx) {
    __shared__ float4 sp[1024];                       // 16KB
    __shared__ ull cbuf[16*128];                      // 16KB
    __shared__ ull ntop[8*32];                        // 2KB
    int tid = threadIdx.x, lane = tid & 31, w = tid >> 5;
    int b = blockIdx.y;
    unsigned lml = (1u << lane) - 1u;
    ull* cb0 = &cbuf[(w*2+0)*128];
    ull* cb1 = &cbuf[(w*2+1)*128];
    ull* nt = &ntop[w*32];

    int qg = blockIdx.x*16 + w*2;
    int s0 = sidx[qg], s1 = sidx[qg+1];
    float qx0 = xyz[(b*3+0)*NN + s0], qy0 = xyz[(b*3+1)*NN + s0], qz0 = xyz[(b*3+2)*NN + s0];
    float qx1 = xyz[(b*3+0)*NN + s1], qy1 = xyz[(b*3+1)*NN + s1], qz1 = xyz[(b*3+2)*NN + s1];
    float c20 = 0.5f*(qx0*qx0 + qy0*qy0 + qz0*qz0);
    float c21 = 0.5f*(qx1*qx1 + qy1*qy1 + qz1*qz1);
    const float INFF = __int_as_float(0x7F800000);
    ull top0 = ~0ull, top1 = ~0ull;
    float thr0 = INFF, thr1 = INFF;
    float u0 = INFF, u1 = INFF;
    int c0 = 0, c1 = 0;

    for (int t = 0; t < NN; t += 1024) {
        __syncthreads();
        #pragma unroll
        for (int j = 0; j < 4; ++j)
            sp[tid + j*256] = g_pxyz[b*NN + t + tid + j*256];
        __syncthreads();
        for (int jj = 0; jj < 1024; jj += 64) {
            if ((c0 | c1) > 64) {      // warp-uniform, rare
                if (c0 > 64) { knn_flush(top0, c0, thr0, cb0, nt, lane); u0 = __fadd_ru(thr0, -c20); }
                if (c1 > 64) { knn_flush(top1, c1, thr1, cb1, nt, lane); u1 = __fadd_ru(thr1, -c21); }
            }
            #pragma unroll
            for (int h = 0; h < 2; ++h) {
                int j = jj + h*32 + lane;
                float4 p = sp[j];
                float d0 = __fmaf_rn(-qx0, p.x, p.w);
                d0 = __fmaf_rn(-qy0, p.y, d0);
                d0 = __fmaf_rn(-qz0, p.z, d0);
                float d1 = __fmaf_rn(-qx1, p.x, p.w);
                d1 = __fmaf_rn(-qy1, p.y, d1);
                d1 = __fmaf_rn(-qz1, p.z, d1);
                bool pr0 = d0 < u0;
                bool pr1 = d1 < u1;
                if (__any_sync(0xffffffffu, pr0 || pr1)) {
                    unsigned m0 = __ballot_sync(0xffffffffu, pr0);
                    unsigned m1 = __ballot_sync(0xffffffffu, pr1);
                    if (pr0) {
                        unsigned ub = mono_map(d0 + c20);
                        cb0[c0 + __popc(m0 & lml)] = ((ull)ub << 32) | (unsigned)(t + j);
                    }
                    if (pr1) {
                        unsigned ub = mono_map(d1 + c21);
                        cb1[c1 + __popc(m1 & lml)] = ((ull)ub << 32) | (unsigned)(t + j);
                    }
                    c0 += __popc(m0);
                    c1 += __popc(m1);
                }
            }
        }
    }
    knn_flush(top0, c0, thr0, cb0, nt, lane);
    knn_flush(top1, c1, thr1, cb1, nt, lane);
    g_idx[(b*NPT + qg + 0)*NS + lane] = (int)(top0 & 0xffffffffu);
    g_idx[(b*NPT + qg + 1)*NS + lane] = (int)(top1 & 0xffffffffu);
}

// ============================================================================
// Layer kernels: split-TF32 mma.sync.m16n8k8, fused BN-stat reduction.
// Block = 256 threads = 8 warps; tile = 128 rows (4 complete centroids).
// ============================================================================

// ---------------- layer1: feat(72 padded) @ W1^T + b1 -> g_h1 + stats ----------------
__global__ __launch_bounds__(256, 2) void k_layer1(const float* __restrict__ xyz,
                                                   const int* __restrict__ sidx,
                                                   const float* __restrict__ b1) {
    __shared__ u32 bhs[72*BPAD];
    __shared__ u32 bls[72*BPAD];
    __shared__ float bs[64];
    __shared__ float sm_s[512], sm_q[512];
    int tid = threadIdx.x;
    for (int i = tid; i < 72*64; i += 256) {
        int k = i >> 6, n = i & 63;
        bhs[k*BPAD + n] = g_w1h[i];
        bls[k*BPAD + n] = g_w1l[i];
    }
    if (tid < 64) bs[tid] = b1[tid];
    __syncthreads();

    int lane = tid & 31, w = tid >> 5;
    int g = lane >> 2, c = lane & 3;
    int row0 = blockIdx.x*128 + w*16 + g;
    int row1 = row0 + 8;
    int b = row0 >> 16;
    int n0 = g_idx[row0], n1 = g_idx[row1];
    int p0 = (row0 >> 5) & (NPT-1);
    int s = sidx[p0];
    float qx = xyz[(b*3+0)*NN + s], qy = xyz[(b*3+1)*NN + s], qz = xyz[(b*3+2)*NN + s];
    float4 P0 = g_pxyz[b*NN + n0];
    float4 P1 = g_pxyz[b*NN + n1];
    const float* f0 = &g_ptst[(size_t)(b*NN + n0)*64];
    const float* f1 = &g_ptst[(size_t)(b*NN + n1)*64];

    u32 ah[9][4], al[9][4];
    #pragma unroll
    for (int t = 0; t < 16; ++t) {
        int col = c + 4*t;
        float x0 = __ldg(&f0[col]);
        float x1 = __ldg(&f1[col]);
        int k = t >> 1, sl = (t & 1)*2;
        tf32_split(x0, ah[k][sl],   al[k][sl]);
        tf32_split(x1, ah[k][sl+1], al[k][sl+1]);
    }
    {
        float e0 = (c == 0) ? (P0.x - qx) : (c == 1) ? (P0.y - qy) : (c == 2) ? (P0.z - qz) : 0.0f;
        float e1 = (c == 0) ? (P1.x - qx) : (c == 1) ? (P1.y - qy) : (c == 2) ? (P1.z - qz) : 0.0f;
        tf32_split(e0, ah[8][0], al[8][0]);
        tf32_split(e1, ah[8][1], al[8][1]);
        ah[8][2] = 0; al[8][2] = 0;
        ah[8][3] = 0; al[8][3] = 0;
    }

    const u32* bhp = &bhs[c*BPAD + g];
    const u32* blp = &bls[c*BPAD + g];
    #pragma unroll
    for (int n8 = 0; n8 < 8; ++n8) {
        float d0 = bs[n8*8 + 2*c], d1 = bs[n8*8 + 2*c + 1];
        float d2 = d0, d3 = d1;
        #pragma unroll
        for (int k = 0; k < 9; ++k) {
            int off = k*8*BPAD + n8*8;
            u32 b0h = bhp[off], b1h = bhp[off + 4*BPAD];
            u32 b0l = blp[off], b1l = blp[off + 4*BPAD];
            mma_tf32(d0,d1,d2,d3, ah[k][0],ah[k][1],ah[k][2],ah[k][3], b0h,b1h);
            mma_tf32(d0,d1,d2,d3, ah[k][0],ah[k][1],ah[k][2],ah[k][3], b0l,b1l);
            mma_tf32(d0,d1,d2,d3, al[k][0],al[k][1],al[k][2],al[k][3], b0h,b1h);
        }
        *(float2*)&g_h1[(size_t)row0*64 + n8*8 + 2*c] = make_float2(d0, d1);
        *(float2*)&g_h1[(size_t)row1*64 + n8*8 + 2*c] = make_float2(d2, d3);
        float s0 = d0 + d2, s1 = d1 + d3;
        float q0 = d0*d0 + d2*d2, q1 = d1*d1 + d3*d3;
        #pragma unroll
        for (int m = 4; m <= 16; m <<= 1) {
            s0 += __shfl_xor_sync(0xffffffffu, s0, m);
            s1 += __shfl_xor_sync(0xffffffffu, s1, m);
            q0 += __shfl_xor_sync(0xffffffffu, q0, m);
            q1 += __shfl_xor_sync(0xffffffffu, q1, m);
        }
        if (lane < 4) {
            int col0 = n8*8 + 2*c;
            sm_s[w*64 + col0] = s0; sm_s[w*64 + col0 + 1] = s1;
            sm_q[w*64 + col0] = q0; sm_q[w*64 + col0 + 1] = q1;
        }
    }
    __syncthreads();
    if (tid < 64) {
        float S = 0.0f, Q = 0.0f;
        #pragma unroll
        for (int ww = 0; ww < 8; ++ww) { S += sm_s[ww*64 + tid]; Q += sm_q[ww*64 + tid]; }
        atomicAdd(&g_stats[tid], S);
        atomicAdd(&g_stats[64 + tid], Q);
    }
}

// ---------------- layer2: relu(BN1(h1)) @ W2^T + b2 -> g_h2 + stats ----------------
__global__ __launch_bounds__(256, 2) void k_layer2(const float* __restrict__ b2,
                                                   const float* __restrict__ g1,
                                                   const float* __restrict__ be1) {
    __shared__ u32 bhs[64*BPAD];
    __shared__ u32 bls[64*BPAD];
    __shared__ float bs[64], sc[64], sh[64];
    __shared__ float sm_s[512], sm_q[512];
    int tid = threadIdx.x;
    for (int i = tid; i < 64*64; i += 256) {
        int k = i >> 6, n = i & 63;
        bhs[k*BPAD + n] = g_w2h[i];
        bls[k*BPAD + n] = g_w2l[i];
    }
    if (tid < 64) {
        bs[tid] = b2[tid];
        float m = g_stats[tid] * INV_ROWS;
        float v = g_stats[64+tid] * INV_ROWS - m*m;
        float scv = g1[tid] * rsqrtf(v + EPSV);
        sc[tid] = scv;
        sh[tid] = be1[tid] - m*scv;
    }
    __syncthreads();

    int lane = tid & 31, w = tid >> 5;
    int g = lane >> 2, c = lane & 3;
    size_t row0 = (size_t)blockIdx.x*128 + w*16 + g;
    size_t row1 = row0 + 8;
    const float* h0 = &g_h1[row0*64];
    const float* h1p = &g_h1[row1*64];

    u32 ah[8][4], al[8][4];
    #pragma unroll
    for (int t = 0; t < 16; ++t) {
        int col = c + 4*t;
        float scv = sc[col], shv = sh[col];
        float x0 = fmaxf(__ldg(&h0[col]) * scv + shv, 0.0f);
        float x1 = fmaxf(__ldg(&h1p[col]) * scv + shv, 0.0f);
        int k = t >> 1, sl = (t & 1)*2;
        tf32_split(x0, ah[k][sl],   al[k][sl]);
        tf32_split(x1, ah[k][sl+1], al[k][sl+1]);
    }

    const u32* bhp = &bhs[c*BPAD + g];
    const u32* blp = &bls[c*BPAD + g];
    #pragma unroll
    for (int n8 = 0; n8 < 8; ++n8) {
        float d0 = bs[n8*8 + 2*c], d1 = bs[n8*8 + 2*c + 1];
        float d2 = d0, d3 = d1;
        #pragma unroll
        for (int k = 0; k < 8; ++k) {
            int off = k*8*BPAD + n8*8;
            u32 b0h = bhp[off], b1h = bhp[off + 4*BPAD];
            u32 b0l = blp[off], b1l = blp[off + 4*BPAD];
            mma_tf32(d0,d1,d2,d3, ah[k][0],ah[k][1],ah[k][2],ah[k][3], b0h,b1h);
            mma_tf32(d0,d1,d2,d3, ah[k][0],ah[k][1],ah[k][2],ah[k][3], b0l,b1l);
            mma_tf32(d0,d1,d2,d3, al[k][0],al[k][1],al[k][2],al[k][3], b0h,b1h);
        }
        *(float2*)&g_h2[row0*64 + n8*8 + 2*c] = make_float2(d0, d1);
        *(float2*)&g_h2[row1*64 + n8*8 + 2*c] = make_float2(d2, d3);
        float s0 = d0 + d2, s1 = d1 + d3;
        float q0 = d0*d0 + d2*d2, q1 = d1*d1 + d3*d3;
        #pragma unroll
        for (int m = 4; m <= 16; m <<= 1) {
            s0 += __shfl_xor_sync(0xffffffffu, s0, m);
            s1 += __shfl_xor_sync(0xffffffffu, s1, m);
            q0 += __shfl_xor_sync(0xffffffffu, q0, m);
            q1 += __shfl_xor_sync(0xffffffffu, q1, m);
        }
        if (lane < 4) {
            int col0 = n8*8 + 2*c;
            sm_s[w*64 + col0] = s0; sm_s[w*64 + col0 + 1] = s1;
            sm_q[w*64 + col0] = q0; sm_q[w*64 + col0 + 1] = q1;
        }
    }
    __syncthreads();
    if (tid < 64) {
        float S = 0.0f, Q = 0.0f;
        #pragma unroll
        for (int ww = 0; ww < 8; ++ww) { S += sm_s[ww*64 + tid]; Q += sm_q[ww*64 + tid]; }
        atomicAdd(&g_stats[128 + tid], S);
        atomicAdd(&g_stats[192 + tid], Q);
    }
}

// ---------------- layer3: relu(BN2(h2)) @ W3^T + b3, fused pool (max/min) + stats ----
// Block = 128 rows = 4 complete centroids; h3 never materialized.
__global__ __launch_bounds__(256, 2) void k_layer3(const float* __restrict__ b3,
                                                   const float* __restrict__ g2,
                                                   const float* __restrict__ be2) {
    __shared__ u32 bhs[64*BPAD];
    __shared__ u32 bls[64*BPAD];
    __shared__ float bs[64], sc[64], sh[64];
    __shared__ float sm_mx[512], sm_mn[512], sm_s[512], sm_q[512];
    int tid = threadIdx.x;
    int lane = tid & 31, w = tid >> 5;
    int g = lane >> 2, c = lane & 3;

    // stage half-0 weights + BN2 affine
    for (int i = tid; i < 64*64; i += 256) {
        int k = i >> 6, n = i & 63;
        bhs[k*BPAD + n] = g_w3h[k*128 + n];
        bls[k*BPAD + n] = g_w3l[k*128 + n];
    }
    if (tid < 64) {
        bs[tid] = b3[tid];
        float m = g_stats[128+tid] * INV_ROWS;
        float v = g_stats[192+tid] * INV_ROWS - m*m;
        float scv = g2[tid] * rsqrtf(v + EPSV);
        sc[tid] = scv;
        sh[tid] = be2[tid] - m*scv;
    }
    __syncthreads();

    size_t row0 = (size_t)blockIdx.x*128 + w*16 + g;
    size_t row1 = row0 + 8;
    const float* h0 = &g_h2[row0*64];
    const float* h1p = &g_h2[row1*64];

    u32 ah[8][4], al[8][4];
    #pragma unroll
    for (int t = 0; t < 16; ++t) {
        int col = c + 4*t;
        float scv = sc[col], shv = sh[col];
        float x0 = fmaxf(__ldg(&h0[col]) * scv + shv, 0.0f);
        float x1 = fmaxf(__ldg(&h1p[col]) * scv + shv, 0.0f);
        int k = t >> 1, sl = (t & 1)*2;
        tf32_split(x0, ah[k][sl],   al[k][sl]);
        tf32_split(x1, ah[k][sl+1], al[k][sl+1]);
    }

    const u32* bhp = &bhs[c*BPAD + g];
    const u32* blp = &bls[c*BPAD + g];

    #pragma unroll
    for (int oh = 0; oh < 2; ++oh) {
        if (oh == 1) {
            __syncthreads();   // pool writes of half 0 consumed below before reuse
            for (int i = tid; i < 64*64; i += 256) {
                int k = i >> 6, n = i & 63;
                bhs[k*BPAD + n] = g_w3h[k*128 + 64 + n];
                bls[k*BPAD + n] = g_w3l[k*128 + 64 + n];
            }
            if (tid < 64) bs[tid] = b3[64 + tid];
            __syncthreads();
        }
        #pragma unroll
        for (int n8 = 0; n8 < 8; ++n8) {
            float d0 = bs[n8*8 + 2*c], d1 = bs[n8*8 + 2*c + 1];
            float d2 = d0, d3 = d1;
            #pragma unroll
            for (int k = 0; k < 8; ++k) {
                int off = k*8*BPAD + n8*8;
                u32 b0h = bhp[off], b1h = bhp[off + 4*BPAD];
                u32 b0l = blp[off], b1l = blp[off + 4*BPAD];
                mma_tf32(d0,d1,d2,d3, ah[k][0],ah[k][1],ah[k][2],ah[k][3], b0h,b1h);
                mma_tf32(d0,d1,d2,d3, ah[k][0],ah[k][1],ah[k][2],ah[k][3], b0l,b1l);
                mma_tf32(d0,d1,d2,d3, al[k][0],al[k][1],al[k][2],al[k][3], b0h,b1h);
            }
            float mx0 = fmaxf(d0, d2), mn0 = fminf(d0, d2);
            float mx1 = fmaxf(d1, d3), mn1 = fminf(d1, d3);
            float s0 = d0 + d2, s1 = d1 + d3;
            float q0 = d0*d0 + d2*d2, q1 = d1*d1 + d3*d3;
            #pragma unroll
            for (int m = 4; m <= 16; m <<= 1) {
                mx0 = fmaxf(mx0, __shfl_xor_sync(0xffffffffu, mx0, m));
                mn0 = fminf(mn0, __shfl_xor_sync(0xffffffffu, mn0, m));
                mx1 = fmaxf(mx1, __shfl_xor_sync(0xffffffffu, mx1, m));
                mn1 = fminf(mn1, __shfl_xor_sync(0xffffffffu, mn1, m));
                s0 += __shfl_xor_sync(0xffffffffu, s0, m);
                s1 += __shfl_xor_sync(0xffffffffu, s1, m);
                q0 += __shfl_xor_sync(0xffffffffu, q0, m);
                q1 += __shfl_xor_sync(0xffffffffu, q1, m);
            }
            if (lane < 4) {
                int col0 = n8*8 + 2*c;
                sm_mx[w*64 + col0] = mx0; sm_mx[w*64 + col0 + 1] = mx1;
                sm_mn[w*64 + col0] = mn0; sm_mn[w*64 + col0 + 1] = mn1;
                sm_s[w*64 + col0] = s0;   sm_s[w*64 + col0 + 1] = s1;
                sm_q[w*64 + col0] = q0;   sm_q[w*64 + col0 + 1] = q1;
            }
        }
        __syncthreads();
        // finalize: 4 centroids x 64 cols
        {
            int ct = tid >> 6, col = tid & 63;
            float mx = fmaxf(sm_mx[(2*ct)*64 + col], sm_mx[(2*ct+1)*64 + col]);
            float mn = fminf(sm_mn[(2*ct)*64 + col], sm_mn[(2*ct+1)*64 + col]);
            size_t bp = (size_t)blockIdx.x*4 + ct;
            g_mx[bp*128 + oh*64 + col] = mx;
            g_mn[bp*128 + oh*64 + col] = mn;
            if (tid < 64) {
                float S = 0.0f, Q = 0.0f;
                #pragma unroll
                for (int ww = 0; ww < 8; ++ww) { S += sm_s[ww*64 + tid]; Q += sm_q[ww*64 + tid]; }
                atomicAdd(&g_stats[256 + oh*64 + tid], S);
                atomicAdd(&g_stats[384 + oh*64 + tid], Q);
            }
        }
    }
}

// ---------------- apply BN3 affine to pooled max/min, transpose-store ----------------
__global__ __launch_bounds__(256) void k_apply(const float* __restrict__ g3,
                                               const float* __restrict__ be3,
                                               float* __restrict__ outp) {
    int i = blockIdx.x*256 + threadIdx.x;      // 16384*128
    int c = i & 127;
    int bp = i >> 7;
    int b = bp >> 11, p = bp & (NPT-1);
    float m = g_stats[256+c] * INV_ROWS;
    float v = g_stats[384+c] * INV_ROWS - m*m;
    float scv = g3[c] * rsqrtf(v + EPSV);
    float sh = be3[c] - m*scv;
    float pick = (scv >= 0.0f) ? g_mx[i] : g_mn[i];
    outp[((size_t)b*128 + c)*NPT + p] = pick*scv + sh;
}

// ---------------- launch ----------------
extern "C" void kernel_launch(void* const* d_in, const int* in_sizes, int n_in,
                              void* d_out, int out_size) {
    const float* xyz    = (const float*)d_in[0];
    const float* points = (const float*)d_in[1];
    const int*   sidx   = (const int*)d_in[2];
    const float* W1 = (const float*)d_in[3];
    const float* b1 = (const float*)d_in[4];
    const float* g1 = (const float*)d_in[5];
    const float* be1 = (const float*)d_in[6];
    const float* W2 = (const float*)d_in[7];
    const float* b2 = (const float*)d_in[8];
    const float* g2 = (const float*)d_in[9];
    const float* be2 = (const float*)d_in[10];
    const float* W3 = (const float*)d_in[11];
    const float* b3 = (const float*)d_in[12];
    const float* g3 = (const float*)d_in[13];
    const float* be3 = (const float*)d_in[14];

    float* outq = (float*)d_out;                 // (B,3,NPT)
    float* outp = outq + (size_t)BB*3*NPT;       // (B,128,NPT)

    const int prep_total = PREP_XPOSE + 72*64 + 4096 + 8192;
    k_prep<<<(prep_total + 255)/256, 256>>>(xyz, points, sidx, W1, W2, W3, outq);
    k_knn<<<dim3(NPT/16, BB), 256>>>(xyz, sidx);
    k_layer1<<<ROWS/128, 256>>>(xyz, sidx, b1);
    k_layer2<<<ROWS/128, 256>>>(b2, g1, be1);
    k_layer3<<<ROWS/128, 256>>>(b3, g2, be2);
    k_apply<<<(BB*NPT*128)/256, 256>>>(g3, be3, outp);
}